// round 8
// baseline (speedup 1.0000x reference)
#include <cuda_runtime.h>
#include <cuda_bf16.h>
#include <cuda_fp16.h>
#include <math.h>
#include <cstdint>

// ---------------------------------------------------------------------------
// Problem constants
// ---------------------------------------------------------------------------
#define DIM   384
#define NH    12
#define HD    32
#define WS    14
#define BATCH 16
#define HH    56
#define WW    56
#define NWIN  256
#define NTOK  196
#define TOK   50176          // NWIN*NTOK

// ---------------------------------------------------------------------------
// Scratch
// ---------------------------------------------------------------------------
__device__ __align__(16) float  g_X0 [(size_t)TOK * DIM];
__device__ __align__(16) __half g_Y  [(size_t)TOK * DIM];
__device__ __align__(16) __half g_QKV[(size_t)TOK * 3 * DIM];
__device__ __align__(16) __half g_ATT[(size_t)TOK * DIM];
__device__ __align__(16) float  g_X1 [(size_t)TOK * DIM];
__device__ __align__(16) __half g_F  [(size_t)TOK * 4 * DIM];
__device__ __align__(16) __half g_Wh [1769472];          // fp16 weights

#define N_QKV  (3 * DIM * DIM)          // 442368
#define N_PROJ (DIM * DIM)              // 147456
#define N_FC   (4 * DIM * DIM)          // 589824
#define WOFF_QKV  0
#define WOFF_PROJ N_QKV
#define WOFF_FC1  (WOFF_PROJ + N_PROJ)
#define WOFF_FC2  (WOFF_FC1 + N_FC)

// ---------------------------------------------------------------------------
// helpers
// ---------------------------------------------------------------------------
__device__ __forceinline__ uint32_t smem_u32(const void* p) {
    uint32_t a;
    asm("{ .reg .u64 t; cvta.to.shared.u64 t, %1; cvt.u32.u64 %0, t; }" : "=r"(a) : "l"(p));
    return a;
}
__device__ __forceinline__ void cp16(uint32_t dst, const void* src) {
    asm volatile("cp.async.cg.shared.global [%0], [%1], 16;" :: "r"(dst), "l"(src));
}
#define CP_COMMIT() asm volatile("cp.async.commit_group;" ::: "memory")
#define CP_WAIT1()  asm volatile("cp.async.wait_group 1;" ::: "memory")

__device__ __forceinline__ void ldsm_x4(uint32_t* r, uint32_t a) {
    asm volatile("ldmatrix.sync.aligned.m8n8.x4.shared.b16 {%0,%1,%2,%3}, [%4];"
                 : "=r"(r[0]), "=r"(r[1]), "=r"(r[2]), "=r"(r[3]) : "r"(a));
}
__device__ __forceinline__ void ldsm_x4_t(uint32_t* r, uint32_t a) {
    asm volatile("ldmatrix.sync.aligned.m8n8.x4.trans.shared.b16 {%0,%1,%2,%3}, [%4];"
                 : "=r"(r[0]), "=r"(r[1]), "=r"(r[2]), "=r"(r[3]) : "r"(a));
}
__device__ __forceinline__ void mma_f16(float* d, const uint32_t* a, const uint32_t* b) {
    asm volatile(
        "mma.sync.aligned.m16n8k16.row.col.f32.f16.f16.f32 "
        "{%0,%1,%2,%3}, {%4,%5,%6,%7}, {%8,%9}, {%0,%1,%2,%3};"
        : "+f"(d[0]), "+f"(d[1]), "+f"(d[2]), "+f"(d[3])
        : "r"(a[0]), "r"(a[1]), "r"(a[2]), "r"(a[3]), "r"(b[0]), "r"(b[1]));
}
__device__ __forceinline__ uint32_t pack_h2(float x, float y) {
    __half2 h = __floats2half2_rn(x, y);
    return *reinterpret_cast<uint32_t*>(&h);
}

// ---------------------------------------------------------------------------
// 0) all four weight conversions in ONE launch
// ---------------------------------------------------------------------------
__global__ void cvtw_all_kernel(const float* __restrict__ qkv_w,
                                const float* __restrict__ proj_w,
                                const float* __restrict__ fc1_w,
                                const float* __restrict__ fc2_w,
                                __half* __restrict__ dst)
{
    int i = blockIdx.x * blockDim.x + threadIdx.x;
    if (i >= 1769472) return;
    float v;
    if (i < WOFF_PROJ)                v = qkv_w[i];
    else if (i < WOFF_FC1)            v = proj_w[i - WOFF_PROJ];
    else if (i < WOFF_FC2)            v = fc1_w[i - WOFF_FC1];
    else                              v = fc2_w[i - WOFF_FC2];
    dst[i] = __float2half_rn(v);
}

// ---------------------------------------------------------------------------
// 1) depthwise 3x3 conv PE + residual -> windowed (wi,n,c)
// ---------------------------------------------------------------------------
__global__ void conv_pe_kernel(const float* __restrict__ x,
                               const float* __restrict__ cw,
                               const float* __restrict__ cb,
                               float* __restrict__ X0)
{
    const int cg = blockIdx.x * 8;
    const int h  = blockIdx.y;
    const int b  = blockIdx.z;

    __shared__ float sm[8][3][58];

    const int tid = threadIdx.y * 8 + threadIdx.x;
    const int lc  = tid / 56;
    const int lw  = tid % 56;

    const float* xp = x + ((size_t)(b * DIM + cg + lc) * HH) * WW;
#pragma unroll
    for (int r = 0; r < 3; r++) {
        int hh = h - 1 + r;
        float v = (hh >= 0 && hh < HH) ? xp[hh * WW + lw] : 0.0f;
        sm[lc][r][lw + 1] = v;
        if (lw == 0)  sm[lc][r][0]  = 0.0f;
        if (lw == 55) sm[lc][r][57] = 0.0f;
    }
    __syncthreads();

    const int c = threadIdx.x;
    const int w = threadIdx.y;

    float wreg[9];
    const float* cwp = cw + (size_t)(cg + c) * 9;
#pragma unroll
    for (int i = 0; i < 9; i++) wreg[i] = cwp[i];

    float pe = 0.0f;
#pragma unroll
    for (int kh = 0; kh < 3; kh++)
#pragma unroll
        for (int kw = 0; kw < 3; kw++)
            pe += wreg[kh * 3 + kw] * sm[c][kh][w + kw];

    float val = sm[c][1][w + 1] + pe + cb[cg + c];

    const int wi = (b * 4 + h / WS) * 4 + (w / WS);
    const int n  = (h % WS) * WS + (w % WS);
    X0[((size_t)wi * NTOK + n) * DIM + cg + c] = val;
}

// ---------------------------------------------------------------------------
// 2) LayerNorm; fp16 output (GEMM A operand)
// ---------------------------------------------------------------------------
__global__ void ln_kernel(const float* __restrict__ X,
                          const float* __restrict__ gamma,
                          const float* __restrict__ beta,
                          __half* __restrict__ Y)
{
    const int warp = (blockIdx.x * blockDim.x + threadIdx.x) >> 5;
    const int lane = threadIdx.x & 31;
    if (warp >= TOK) return;

    const float* xp = X + (size_t)warp * DIM;
    float v[12];
    float s = 0.0f;
#pragma unroll
    for (int k = 0; k < 12; k++) { v[k] = xp[lane + 32 * k]; s += v[k]; }
#pragma unroll
    for (int o = 16; o; o >>= 1) s += __shfl_xor_sync(0xffffffffu, s, o);
    const float mean = s * (1.0f / DIM);

    float q = 0.0f;
#pragma unroll
    for (int k = 0; k < 12; k++) { float d = v[k] - mean; q += d * d; }
#pragma unroll
    for (int o = 16; o; o >>= 1) q += __shfl_xor_sync(0xffffffffu, q, o);
    const float inv = rsqrtf(q * (1.0f / DIM) + 1e-5f);

    __half* yp = Y + (size_t)warp * DIM;
#pragma unroll
    for (int k = 0; k < 12; k++) {
        int c = lane + 32 * k;
        yp[c] = __float2half_rn((v[k] - mean) * inv * gamma[c] + beta[c]);
    }
}

// ---------------------------------------------------------------------------
// 3) FP16 mma.sync GEMM: C[M,N] = act(A[M,K] @ W[N,K]^T + bias) (+ R)
//    CTA 128x128, BK=64, 4 warps (2m x 2n), warp 64x64 (low smem-bytes/MAC).
//    3-stage cp.async (110.6KB) -> 2 CTAs/SM. 144B odd-stride rows.
// ---------------------------------------------------------------------------
#define BM 128
#define BN 128
#define BK 64
#define ROW_B 144                            // 9 granules, odd -> conflict-free
#define A_BYTES (128 * ROW_B)                // 18432
#define STAGE_B (2 * A_BYTES)                // 36864
#define NSTAGE  3
#define GEMM_SMEM (NSTAGE * STAGE_B)         // 110592

__global__ __launch_bounds__(128, 2)
void hgemm_kernel(const __half* __restrict__ A,
                  const __half* __restrict__ W,
                  const float* __restrict__ bias,
                  const float* __restrict__ R,
                  float* __restrict__ Cf,
                  __half* __restrict__ Ch,
                  int M, int N, int K, int act)
{
    extern __shared__ char smc[];
    const uint32_t smem_base = smem_u32(smc);
    const int tid  = threadIdx.x;
    const int lane = tid & 31;
    const int wid  = tid >> 5;
    const int bm = blockIdx.y * BM;
    const int bn = blockIdx.x * BN;

    const int warp_m = (wid & 1) * 64;
    const int warp_n = (wid >> 1) * 64;

    float acc[4][8][4];
#pragma unroll
    for (int im = 0; im < 4; im++)
#pragma unroll
        for (int in = 0; in < 8; in++)
#pragma unroll
            for (int j = 0; j < 4; j++) acc[im][in][j] = 0.0f;

    // ldmatrix lane geometry
    const int g  = lane >> 3;
    const int r8 = lane & 7;
    const int a_row = warp_m + (g & 1) * 8 + r8;     // + im*16
    const int a_cg  = g >> 1;                        // 16B chunk within k16
    const int b_row = warp_n + (g >> 1) * 8 + r8;    // + inp*16
    const int b_cg  = g & 1;

    const int NC = K >> 6;

    // fill: thread t -> row t (A and B), 8 chunks of 16B each
    auto fill = [&](int kc, int st) {
        const int k0 = kc << 6;
        const uint32_t sb = smem_base + (uint32_t)st * STAGE_B;
        const __half* Ag = A + (size_t)(bm + tid) * K + k0;
        const __half* Wg = W + (size_t)(bn + tid) * K + k0;
#pragma unroll
        for (int c = 0; c < 8; c++) {
            const uint32_t so = (uint32_t)(tid * ROW_B + c * 16);
            cp16(sb + so, Ag + c * 8);
            cp16(sb + A_BYTES + so, Wg + c * 8);
        }
    };

    fill(0, 0); CP_COMMIT();
    fill(1, 1); CP_COMMIT();

    for (int kc = 0; kc < NC; kc++) {
        CP_WAIT1();
        __syncthreads();

        if (kc + 2 < NC) fill(kc + 2, (kc + 2) % NSTAGE);
        CP_COMMIT();                      // unconditional: constant depth

        const uint32_t ab = smem_base + (uint32_t)(kc % NSTAGE) * STAGE_B;
        const uint32_t bb = ab + A_BYTES;

#pragma unroll
        for (int s = 0; s < 4; s++) {
            uint32_t af[4][4], bf[4][4];
#pragma unroll
            for (int im = 0; im < 4; im++)
                ldsm_x4(af[im], ab + (uint32_t)((a_row + im * 16) * ROW_B +
                                                (s * 2 + a_cg) * 16));
#pragma unroll
            for (int inp = 0; inp < 4; inp++)
                ldsm_x4(bf[inp], bb + (uint32_t)((b_row + inp * 16) * ROW_B +
                                                 (s * 2 + b_cg) * 16));
#pragma unroll
            for (int im = 0; im < 4; im++)
#pragma unroll
                for (int in = 0; in < 8; in++)
                    mma_f16(acc[im][in], af[im], &bf[in >> 1][(in & 1) * 2]);
        }
    }

    // epilogue
    const int rq = lane >> 2;
    const int cq = (lane & 3) * 2;
#pragma unroll
    for (int im = 0; im < 4; im++) {
        const int row0 = bm + warp_m + im * 16 + rq;
#pragma unroll
        for (int in = 0; in < 8; in++) {
            const int col = bn + warp_n + in * 8 + cq;
            const float2 bv = *(const float2*)(bias + col);
            float v0 = acc[im][in][0] + bv.x;
            float v1 = acc[im][in][1] + bv.y;
            float v2 = acc[im][in][2] + bv.x;
            float v3 = acc[im][in][3] + bv.y;
            if (act == 1) {
                v0 = 0.5f * v0 * (1.0f + erff(v0 * 0.70710678118654752f));
                v1 = 0.5f * v1 * (1.0f + erff(v1 * 0.70710678118654752f));
                v2 = 0.5f * v2 * (1.0f + erff(v2 * 0.70710678118654752f));
                v3 = 0.5f * v3 * (1.0f + erff(v3 * 0.70710678118654752f));
            }
            if (Ch) {
                *(__half2*)(Ch + (size_t)row0 * N + col) =
                    __halves2half2(__float2half_rn(v0), __float2half_rn(v1));
                *(__half2*)(Ch + (size_t)(row0 + 8) * N + col) =
                    __halves2half2(__float2half_rn(v2), __float2half_rn(v3));
            } else {
                if (R) {
                    const float2 r0 = *(const float2*)(R + (size_t)row0 * N + col);
                    const float2 r1 = *(const float2*)(R + (size_t)(row0 + 8) * N + col);
                    v0 += r0.x; v1 += r0.y; v2 += r1.x; v3 += r1.y;
                }
                *(float2*)(Cf + (size_t)row0 * N + col)       = make_float2(v0, v1);
                *(float2*)(Cf + (size_t)(row0 + 8) * N + col) = make_float2(v2, v3);
            }
        }
    }
}

// ---------------------------------------------------------------------------
// 4) Window attention, full fp16 mma. 128 threads (4 warps), occupancy 2.
//    S accumulators repack DIRECTLY into PV A-fragments (no P smem).
// ---------------------------------------------------------------------------
#define AQ_STR 40
#define AROWS  208
#define ATTN_SMEM (3 * AROWS * AQ_STR * 2)      // 49920 B

__global__ __launch_bounds__(128, 2)
void attn_h_kernel(const __half* __restrict__ QKV, __half* __restrict__ ATT)
{
    const int wi  = blockIdx.x / NH;
    const int hdi = blockIdx.x % NH;

    extern __shared__ __half shh[];
    __half* qs = shh;
    __half* ks = qs + AROWS * AQ_STR;
    __half* vs = ks + AROWS * AQ_STR;

    const int tid  = threadIdx.x;
    const int warp = tid >> 5;
    const int lane = tid & 31;
    const float scale = 0.1767766952966369f;   // 1/sqrt(32)

    const __half* base = QKV + (size_t)wi * NTOK * (3 * DIM) + hdi * HD;
    for (int idx = tid; idx < AROWS * 4; idx += 128) {
        const int row = idx >> 2, c = idx & 3;
        uint4 q = make_uint4(0, 0, 0, 0), k = q, v = q;
        if (row < NTOK) {
            const __half* src = base + (size_t)row * (3 * DIM) + c * 8;
            q = *(const uint4*)(src);
            k = *(const uint4*)(src + DIM);
            v = *(const uint4*)(src + 2 * DIM);
        }
        *(uint4*)(qs + row * AQ_STR + c * 8) = q;
        *(uint4*)(ks + row * AQ_STR + c * 8) = k;
        *(uint4*)(vs + row * AQ_STR + c * 8) = v;
    }
    __syncthreads();

    const uint32_t qb = smem_u32(qs);
    const uint32_t kb = smem_u32(ks);
    const uint32_t vb = smem_u32(vs);

    const int g  = lane >> 3;
    const int r8 = lane & 7;
    const int a_row_off = (g & 1) * 8 + r8;
    const int a_cg      = (g >> 1) * 16;
    const int b_row_off = (g >> 1) * 8 + r8;
    const int b_cg      = (g & 1) * 16;

    const int rq  = lane >> 2;
    const int cq2 = (lane & 3) * 2;

    for (int t = warp; t < 13; t += 4) {
        const int m0 = t * 16;

        uint32_t af[2][4];
#pragma unroll
        for (int s = 0; s < 2; s++)
            ldsm_x4(af[s], qb + (uint32_t)((m0 + a_row_off) * 80 + a_cg + s * 32));

        float c[26][4];
#pragma unroll
        for (int nt = 0; nt < 26; nt++) { c[nt][0] = c[nt][1] = c[nt][2] = c[nt][3] = 0.f; }
#pragma unroll
        for (int np = 0; np < 13; np++) {
#pragma unroll
            for (int s = 0; s < 2; s++) {
                uint32_t bf[4];
                ldsm_x4(bf, kb + (uint32_t)((np * 16 + b_row_off) * 80 + b_cg + s * 32));
                mma_f16(c[2 * np],     af[s], &bf[0]);
                mma_f16(c[2 * np + 1], af[s], &bf[2]);
            }
        }

        float mx0 = -1e30f, mx1 = -1e30f;
#pragma unroll
        for (int nt = 0; nt < 26; nt++) {
            const int col = nt * 8 + cq2;
            if (col < NTOK)     { mx0 = fmaxf(mx0, c[nt][0]); mx1 = fmaxf(mx1, c[nt][2]); }
            if (col + 1 < NTOK) { mx0 = fmaxf(mx0, c[nt][1]); mx1 = fmaxf(mx1, c[nt][3]); }
        }
        mx0 = fmaxf(mx0, __shfl_xor_sync(0xffffffffu, mx0, 1));
        mx0 = fmaxf(mx0, __shfl_xor_sync(0xffffffffu, mx0, 2));
        mx1 = fmaxf(mx1, __shfl_xor_sync(0xffffffffu, mx1, 1));
        mx1 = fmaxf(mx1, __shfl_xor_sync(0xffffffffu, mx1, 2));

        uint32_t ph[26][2];
        float sum0 = 0.f, sum1 = 0.f;
#pragma unroll
        for (int nt = 0; nt < 26; nt++) {
            const int col = nt * 8 + cq2;
            float p0 = (col < NTOK)     ? __expf((c[nt][0] - mx0) * scale) : 0.f;
            float p1 = (col + 1 < NTOK) ? __expf((c[nt][1] - mx0) * scale) : 0.f;
            float p2 = (col < NTOK)     ? __expf((c[nt][2] - mx1) * scale) : 0.f;
            float p3 = (col + 1 < NTOK) ? __expf((c[nt][3] - mx1) * scale) : 0.f;
            sum0 += p0 + p1;
            sum1 += p2 + p3;
            ph[nt][0] = pack_h2(p0, p1);
            ph[nt][1] = pack_h2(p2, p3);
        }
        sum0 += __shfl_xor_sync(0xffffffffu, sum0, 1);
        sum0 += __shfl_xor_sync(0xffffffffu, sum0, 2);
        sum1 += __shfl_xor_sync(0xffffffffu, sum1, 1);
        sum1 += __shfl_xor_sync(0xffffffffu, sum1, 2);

        float o[4][4];
#pragma unroll
        for (int n = 0; n < 4; n++) { o[n][0] = o[n][1] = o[n][2] = o[n][3] = 0.f; }
#pragma unroll
        for (int kt = 0; kt < 13; kt++) {
            uint32_t a[4] = { ph[2 * kt][0], ph[2 * kt][1],
                              ph[2 * kt + 1][0], ph[2 * kt + 1][1] };
            uint32_t v0f[4], v1f[4];
            ldsm_x4_t(v0f, vb + (uint32_t)((kt * 16 + a_row_off) * 80 + a_cg));
            ldsm_x4_t(v1f, vb + (uint32_t)((kt * 16 + a_row_off) * 80 + a_cg + 32));
            mma_f16(o[0], a, &v0f[0]);
            mma_f16(o[1], a, &v0f[2]);
            mma_f16(o[2], a, &v1f[0]);
            mma_f16(o[3], a, &v1f[2]);
        }

        const float inv0 = 1.0f / sum0;
        const float inv1 = 1.0f / sum1;
        const int r0 = m0 + rq, r1 = m0 + rq + 8;
#pragma unroll
        for (int n = 0; n < 4; n++) {
            const int col = hdi * HD + n * 8 + cq2;
            if (r0 < NTOK)
                *(__half2*)(ATT + ((size_t)wi * NTOK + r0) * DIM + col) =
                    __halves2half2(__float2half_rn(o[n][0] * inv0), __float2half_rn(o[n][1] * inv0));
            if (r1 < NTOK)
                *(__half2*)(ATT + ((size_t)wi * NTOK + r1) * DIM + col) =
                    __halves2half2(__float2half_rn(o[n][2] * inv1), __float2half_rn(o[n][3] * inv1));
        }
    }
}

// ---------------------------------------------------------------------------
// 5) Windowed (wi,n,c) -> BCHW output
// ---------------------------------------------------------------------------
__global__ void unwin_kernel(const float* __restrict__ X,
                             float* __restrict__ out)
{
    const int ct = blockIdx.x >> 1, wt = blockIdx.x & 1;
    const int h = blockIdx.y, b = blockIdx.z;
    const int c0 = ct * 32, w0 = wt * 32;

    __shared__ float sm[32][33];
    const int tx = threadIdx.x, ty = threadIdx.y;

#pragma unroll
    for (int k = 0; k < 4; k++) {
        int r = ty + 8 * k;
        int w = w0 + r;
        if (w < WW) {
            int wi = (b * 4 + h / WS) * 4 + w / WS;
            int n  = (h % WS) * WS + (w % WS);
            sm[r][tx] = X[((size_t)wi * NTOK + n) * DIM + c0 + tx];
        }
    }
    __syncthreads();

#pragma unroll
    for (int k = 0; k < 4; k++) {
        int c = c0 + ty + 8 * k;
        int w = w0 + tx;
        if (w < WW)
            out[(((size_t)b * DIM + c) * HH + h) * WW + w] = sm[tx][ty + 8 * k];
    }
}

// ---------------------------------------------------------------------------
// Launch
// ---------------------------------------------------------------------------
extern "C" void kernel_launch(void* const* d_in, const int* in_sizes, int n_in,
                              void* d_out, int out_size)
{
    const float* x      = (const float*)d_in[0];
    const float* conv_w = (const float*)d_in[1];
    const float* conv_b = (const float*)d_in[2];
    const float* ln1_g  = (const float*)d_in[3];
    const float* ln1_b  = (const float*)d_in[4];
    const float* qkv_w  = (const float*)d_in[5];
    const float* qkv_b  = (const float*)d_in[6];
    const float* proj_w = (const float*)d_in[7];
    const float* proj_b = (const float*)d_in[8];
    const float* ln2_g  = (const float*)d_in[9];
    const float* ln2_b  = (const float*)d_in[10];
    const float* fc1_w  = (const float*)d_in[11];
    const float* fc1_b  = (const float*)d_in[12];
    const float* fc2_w  = (const float*)d_in[13];
    const float* fc2_b  = (const float*)d_in[14];
    float* out = (float*)d_out;

    float *X0, *X1;
    __half *Y, *QKV, *ATT, *F, *Wh;
    cudaGetSymbolAddress((void**)&X0,  g_X0);
    cudaGetSymbolAddress((void**)&Y,   g_Y);
    cudaGetSymbolAddress((void**)&QKV, g_QKV);
    cudaGetSymbolAddress((void**)&ATT, g_ATT);
    cudaGetSymbolAddress((void**)&X1,  g_X1);
    cudaGetSymbolAddress((void**)&F,   g_F);
    cudaGetSymbolAddress((void**)&Wh,  g_Wh);

    cudaFuncSetAttribute(attn_h_kernel, cudaFuncAttributeMaxDynamicSharedMemorySize, ATTN_SMEM);
    cudaFuncSetAttribute(hgemm_kernel, cudaFuncAttributeMaxDynamicSharedMemorySize, GEMM_SMEM);

    // 0) fp16 weights (single launch)
    cvtw_all_kernel<<<(1769472 + 255) / 256, 256>>>(qkv_w, proj_w, fc1_w, fc2_w, Wh);

    // 1) conv PE + residual -> X0
    conv_pe_kernel<<<dim3(DIM / 8, HH, BATCH), dim3(8, 56)>>>(x, conv_w, conv_b, X0);

    // 2) LN1 -> Y (fp16)
    ln_kernel<<<TOK / 8, 256>>>(X0, ln1_g, ln1_b, Y);

    // 3) QKV GEMM (fp16 in, fp16 out)
    hgemm_kernel<<<dim3(3 * DIM / BN, TOK / BM), 128, GEMM_SMEM>>>(
        Y, Wh + WOFF_QKV, qkv_b, nullptr, nullptr, QKV, TOK, 3 * DIM, DIM, 0);

    // 4) window attention -> ATT (fp16)
    attn_h_kernel<<<NWIN * NH, 128, ATTN_SMEM>>>(QKV, ATT);

    // 5) proj GEMM + residual(X0) -> X1 (fp32)
    hgemm_kernel<<<dim3(DIM / BN, TOK / BM), 128, GEMM_SMEM>>>(
        ATT, Wh + WOFF_PROJ, proj_b, X0, X1, nullptr, TOK, DIM, DIM, 0);

    // 6) LN2 -> Y (fp16)
    ln_kernel<<<TOK / 8, 256>>>(X1, ln2_g, ln2_b, Y);

    // 7) FC1 GEMM + GELU -> F (fp16)
    hgemm_kernel<<<dim3(4 * DIM / BN, TOK / BM), 128, GEMM_SMEM>>>(
        Y, Wh + WOFF_FC1, fc1_b, nullptr, nullptr, F, TOK, 4 * DIM, DIM, 1);

    // 8) FC2 GEMM + residual(X1) -> X0 (fp32)
    hgemm_kernel<<<dim3(DIM / BN, TOK / BM), 128, GEMM_SMEM>>>(
        F, Wh + WOFF_FC2, fc2_b, X1, X0, nullptr, TOK, DIM, 4 * DIM, 0);

    // 9) un-window -> BCHW
    unwin_kernel<<<dim3(24, HH, BATCH), dim3(32, 8)>>>(X0, out);
}

// round 9
// speedup vs baseline: 1.0424x; 1.0424x over previous
#include <cuda_runtime.h>
#include <cuda_bf16.h>
#include <cuda_fp16.h>
#include <math.h>
#include <cstdint>

// ---------------------------------------------------------------------------
// Problem constants
// ---------------------------------------------------------------------------
#define DIM   384
#define NH    12
#define HD    32
#define WS    14
#define BATCH 16
#define HH    56
#define WW    56
#define NWIN  256
#define NTOK  196
#define TOK   50176          // NWIN*NTOK

// ---------------------------------------------------------------------------
// Scratch
// ---------------------------------------------------------------------------
__device__ __align__(16) float  g_X0 [(size_t)TOK * DIM];
__device__ __align__(16) __half g_Y  [(size_t)TOK * DIM];
__device__ __align__(16) __half g_QKV[(size_t)TOK * 3 * DIM];
__device__ __align__(16) __half g_ATT[(size_t)TOK * DIM];
__device__ __align__(16) float  g_X1 [(size_t)TOK * DIM];
__device__ __align__(16) __half g_F  [(size_t)TOK * 4 * DIM];
__device__ __align__(16) __half g_Wh [1769472];          // fp16 weights

#define N_QKV  (3 * DIM * DIM)
#define N_PROJ (DIM * DIM)
#define N_FC   (4 * DIM * DIM)
#define WOFF_QKV  0
#define WOFF_PROJ N_QKV
#define WOFF_FC1  (WOFF_PROJ + N_PROJ)
#define WOFF_FC2  (WOFF_FC1 + N_FC)

// ---------------------------------------------------------------------------
// helpers
// ---------------------------------------------------------------------------
__device__ __forceinline__ uint32_t smem_u32(const void* p) {
    uint32_t a;
    asm("{ .reg .u64 t; cvta.to.shared.u64 t, %1; cvt.u32.u64 %0, t; }" : "=r"(a) : "l"(p));
    return a;
}
__device__ __forceinline__ void cp16(uint32_t dst, const void* src) {
    asm volatile("cp.async.cg.shared.global [%0], [%1], 16;" :: "r"(dst), "l"(src));
}
#define CP_COMMIT() asm volatile("cp.async.commit_group;" ::: "memory")
#define CP_WAIT1()  asm volatile("cp.async.wait_group 1;" ::: "memory")

__device__ __forceinline__ void ldsm_x4(uint32_t* r, uint32_t a) {
    asm volatile("ldmatrix.sync.aligned.m8n8.x4.shared.b16 {%0,%1,%2,%3}, [%4];"
                 : "=r"(r[0]), "=r"(r[1]), "=r"(r[2]), "=r"(r[3]) : "r"(a));
}
__device__ __forceinline__ void ldsm_x4_t(uint32_t* r, uint32_t a) {
    asm volatile("ldmatrix.sync.aligned.m8n8.x4.trans.shared.b16 {%0,%1,%2,%3}, [%4];"
                 : "=r"(r[0]), "=r"(r[1]), "=r"(r[2]), "=r"(r[3]) : "r"(a));
}
__device__ __forceinline__ void mma_f16(float* d, const uint32_t* a, const uint32_t* b) {
    asm volatile(
        "mma.sync.aligned.m16n8k16.row.col.f32.f16.f16.f32 "
        "{%0,%1,%2,%3}, {%4,%5,%6,%7}, {%8,%9}, {%0,%1,%2,%3};"
        : "+f"(d[0]), "+f"(d[1]), "+f"(d[2]), "+f"(d[3])
        : "r"(a[0]), "r"(a[1]), "r"(a[2]), "r"(a[3]), "r"(b[0]), "r"(b[1]));
}
__device__ __forceinline__ uint32_t pack_h2(float x, float y) {
    __half2 h = __floats2half2_rn(x, y);
    return *reinterpret_cast<uint32_t*>(&h);
}

// ---------------------------------------------------------------------------
// 0) all four weight conversions in ONE launch
// ---------------------------------------------------------------------------
__global__ void cvtw_all_kernel(const float* __restrict__ qkv_w,
                                const float* __restrict__ proj_w,
                                const float* __restrict__ fc1_w,
                                const float* __restrict__ fc2_w,
                                __half* __restrict__ dst)
{
    int i = blockIdx.x * blockDim.x + threadIdx.x;
    if (i >= 1769472) return;
    float v;
    if (i < WOFF_PROJ)                v = qkv_w[i];
    else if (i < WOFF_FC1)            v = proj_w[i - WOFF_PROJ];
    else if (i < WOFF_FC2)            v = fc1_w[i - WOFF_FC1];
    else                              v = fc2_w[i - WOFF_FC2];
    dst[i] = __float2half_rn(v);
}

// ---------------------------------------------------------------------------
// 1) depthwise 3x3 conv PE + residual -> windowed (wi,n,c)
// ---------------------------------------------------------------------------
__global__ void conv_pe_kernel(const float* __restrict__ x,
                               const float* __restrict__ cw,
                               const float* __restrict__ cb,
                               float* __restrict__ X0)
{
    const int cg = blockIdx.x * 8;
    const int h  = blockIdx.y;
    const int b  = blockIdx.z;

    __shared__ float sm[8][3][58];

    const int tid = threadIdx.y * 8 + threadIdx.x;
    const int lc  = tid / 56;
    const int lw  = tid % 56;

    const float* xp = x + ((size_t)(b * DIM + cg + lc) * HH) * WW;
#pragma unroll
    for (int r = 0; r < 3; r++) {
        int hh = h - 1 + r;
        float v = (hh >= 0 && hh < HH) ? xp[hh * WW + lw] : 0.0f;
        sm[lc][r][lw + 1] = v;
        if (lw == 0)  sm[lc][r][0]  = 0.0f;
        if (lw == 55) sm[lc][r][57] = 0.0f;
    }
    __syncthreads();

    const int c = threadIdx.x;
    const int w = threadIdx.y;

    float wreg[9];
    const float* cwp = cw + (size_t)(cg + c) * 9;
#pragma unroll
    for (int i = 0; i < 9; i++) wreg[i] = cwp[i];

    float pe = 0.0f;
#pragma unroll
    for (int kh = 0; kh < 3; kh++)
#pragma unroll
        for (int kw = 0; kw < 3; kw++)
            pe += wreg[kh * 3 + kw] * sm[c][kh][w + kw];

    float val = sm[c][1][w + 1] + pe + cb[cg + c];

    const int wi = (b * 4 + h / WS) * 4 + (w / WS);
    const int n  = (h % WS) * WS + (w % WS);
    X0[((size_t)wi * NTOK + n) * DIM + cg + c] = val;
}

// ---------------------------------------------------------------------------
// 2) LayerNorm; fp16 output (GEMM A operand)
// ---------------------------------------------------------------------------
__global__ void ln_kernel(const float* __restrict__ X,
                          const float* __restrict__ gamma,
                          const float* __restrict__ beta,
                          __half* __restrict__ Y)
{
    const int warp = (blockIdx.x * blockDim.x + threadIdx.x) >> 5;
    const int lane = threadIdx.x & 31;
    if (warp >= TOK) return;

    const float* xp = X + (size_t)warp * DIM;
    float v[12];
    float s = 0.0f;
#pragma unroll
    for (int k = 0; k < 12; k++) { v[k] = xp[lane + 32 * k]; s += v[k]; }
#pragma unroll
    for (int o = 16; o; o >>= 1) s += __shfl_xor_sync(0xffffffffu, s, o);
    const float mean = s * (1.0f / DIM);

    float q = 0.0f;
#pragma unroll
    for (int k = 0; k < 12; k++) { float d = v[k] - mean; q += d * d; }
#pragma unroll
    for (int o = 16; o; o >>= 1) q += __shfl_xor_sync(0xffffffffu, q, o);
    const float inv = rsqrtf(q * (1.0f / DIM) + 1e-5f);

    __half* yp = Y + (size_t)warp * DIM;
#pragma unroll
    for (int k = 0; k < 12; k++) {
        int c = lane + 32 * k;
        yp[c] = __float2half_rn((v[k] - mean) * inv * gamma[c] + beta[c]);
    }
}

// ---------------------------------------------------------------------------
// 3) FP16 mma.sync GEMM: C[M,N] = act(A[M,K] @ W[N,K]^T + bias) (+ R)
//    CTA 256x128, BK=64, 8 warps (4m x 2n), warp 64x64. Occupancy 1.
//    3-stage cp.async + REGISTER double-buffered ldsm fragments (ILP-based
//    latency hiding, CUTLASS sm80 style). 144B odd-stride rows.
// ---------------------------------------------------------------------------
#define BM 256
#define BN 128
#define BK 64
#define ROW_B 144                            // 9 granules, odd -> conflict-free
#define A_BYTES (BM * ROW_B)                 // 36864
#define B_BYTES (BN * ROW_B)                 // 18432
#define STAGE_B (A_BYTES + B_BYTES)          // 55296
#define NSTAGE  3
#define GEMM_SMEM (NSTAGE * STAGE_B)         // 165888

__global__ __launch_bounds__(256, 1)
void hgemm_kernel(const __half* __restrict__ A,
                  const __half* __restrict__ W,
                  const float* __restrict__ bias,
                  const float* __restrict__ R,
                  float* __restrict__ Cf,
                  __half* __restrict__ Ch,
                  int M, int N, int K, int act)
{
    extern __shared__ char smc[];
    const uint32_t smem_base = smem_u32(smc);
    const int tid  = threadIdx.x;
    const int lane = tid & 31;
    const int wid  = tid >> 5;
    const int bm = blockIdx.y * BM;
    const int bn = blockIdx.x * BN;

    const int warp_m = (wid & 3) * 64;
    const int warp_n = (wid >> 2) * 64;

    float acc[4][8][4];
#pragma unroll
    for (int im = 0; im < 4; im++)
#pragma unroll
        for (int in = 0; in < 8; in++)
#pragma unroll
            for (int j = 0; j < 4; j++) acc[im][in][j] = 0.0f;

    // ldmatrix lane geometry
    const int g  = lane >> 3;
    const int r8 = lane & 7;
    const int a_row = warp_m + (g & 1) * 8 + r8;     // + im*16
    const int a_cg  = g >> 1;                        // 16B chunk within k16
    const int b_row = warp_n + (g >> 1) * 8 + r8;    // + inp*16
    const int b_cg  = g & 1;

    const int NC = K >> 6;

    // fill: A row = tid (8 chunks); B row = tid>>1 (4 chunks)
    const int br  = tid >> 1;
    const int bc0 = (tid & 1) * 4;
    auto fill = [&](int kc, int st) {
        const int k0 = kc << 6;
        const uint32_t sb = smem_base + (uint32_t)st * STAGE_B;
        const __half* Ag = A + (size_t)(bm + tid) * K + k0;
#pragma unroll
        for (int c = 0; c < 8; c++)
            cp16(sb + (uint32_t)(tid * ROW_B + c * 16), Ag + c * 8);
        const __half* Wg = W + (size_t)(bn + br) * K + k0;
#pragma unroll
        for (int c = 0; c < 4; c++) {
            const int cc = bc0 + c;
            cp16(sb + A_BYTES + (uint32_t)(br * ROW_B + cc * 16), Wg + cc * 8);
        }
    };

    fill(0, 0); CP_COMMIT();
    fill(1, 1); CP_COMMIT();

    uint32_t af[2][4][4], bf[2][4][4];

    for (int kc = 0; kc < NC; kc++) {
        CP_WAIT1();
        __syncthreads();

        if (kc + 2 < NC) fill(kc + 2, (kc + 2) % NSTAGE);
        CP_COMMIT();                      // unconditional: constant depth

        const uint32_t ab = smem_base + (uint32_t)(kc % NSTAGE) * STAGE_B;
        const uint32_t bb = ab + A_BYTES;

        // prime s=0 fragments
#pragma unroll
        for (int im = 0; im < 4; im++)
            ldsm_x4(af[0][im], ab + (uint32_t)((a_row + im * 16) * ROW_B + a_cg * 16));
#pragma unroll
        for (int inp = 0; inp < 4; inp++)
            ldsm_x4(bf[0][inp], bb + (uint32_t)((b_row + inp * 16) * ROW_B + b_cg * 16));

#pragma unroll
        for (int s = 0; s < 4; s++) {
            const int cur = s & 1;
            const int nxt = cur ^ 1;
            if (s < 3) {
                // prefetch s+1 fragments BEFORE consuming s (hides LDS latency)
#pragma unroll
                for (int im = 0; im < 4; im++)
                    ldsm_x4(af[nxt][im], ab + (uint32_t)((a_row + im * 16) * ROW_B +
                                                         ((s + 1) * 2 + a_cg) * 16));
#pragma unroll
                for (int inp = 0; inp < 4; inp++)
                    ldsm_x4(bf[nxt][inp], bb + (uint32_t)((b_row + inp * 16) * ROW_B +
                                                          ((s + 1) * 2 + b_cg) * 16));
            }
#pragma unroll
            for (int im = 0; im < 4; im++)
#pragma unroll
                for (int in = 0; in < 8; in++)
                    mma_f16(acc[im][in], af[cur][im], &bf[cur][in >> 1][(in & 1) * 2]);
        }
    }

    // epilogue
    const int rq = lane >> 2;
    const int cq = (lane & 3) * 2;
#pragma unroll
    for (int im = 0; im < 4; im++) {
        const int row0 = bm + warp_m + im * 16 + rq;
#pragma unroll
        for (int in = 0; in < 8; in++) {
            const int col = bn + warp_n + in * 8 + cq;
            const float2 bv = *(const float2*)(bias + col);
            float v0 = acc[im][in][0] + bv.x;
            float v1 = acc[im][in][1] + bv.y;
            float v2 = acc[im][in][2] + bv.x;
            float v3 = acc[im][in][3] + bv.y;
            if (act == 1) {
                v0 = 0.5f * v0 * (1.0f + erff(v0 * 0.70710678118654752f));
                v1 = 0.5f * v1 * (1.0f + erff(v1 * 0.70710678118654752f));
                v2 = 0.5f * v2 * (1.0f + erff(v2 * 0.70710678118654752f));
                v3 = 0.5f * v3 * (1.0f + erff(v3 * 0.70710678118654752f));
            }
            if (Ch) {
                *(__half2*)(Ch + (size_t)row0 * N + col) =
                    __halves2half2(__float2half_rn(v0), __float2half_rn(v1));
                *(__half2*)(Ch + (size_t)(row0 + 8) * N + col) =
                    __halves2half2(__float2half_rn(v2), __float2half_rn(v3));
            } else {
                if (R) {
                    const float2 r0 = *(const float2*)(R + (size_t)row0 * N + col);
                    const float2 r1 = *(const float2*)(R + (size_t)(row0 + 8) * N + col);
                    v0 += r0.x; v1 += r0.y; v2 += r1.x; v3 += r1.y;
                }
                *(float2*)(Cf + (size_t)row0 * N + col)       = make_float2(v0, v1);
                *(float2*)(Cf + (size_t)(row0 + 8) * N + col) = make_float2(v2, v3);
            }
        }
    }
}

// ---------------------------------------------------------------------------
// 4) Window attention, full fp16 mma. 128 threads (4 warps), occupancy 2.
//    S accumulators repack DIRECTLY into PV A-fragments (no P smem).
// ---------------------------------------------------------------------------
#define AQ_STR 40
#define AROWS  208
#define ATTN_SMEM (3 * AROWS * AQ_STR * 2)      // 49920 B

__global__ __launch_bounds__(128, 2)
void attn_h_kernel(const __half* __restrict__ QKV, __half* __restrict__ ATT)
{
    const int wi  = blockIdx.x / NH;
    const int hdi = blockIdx.x % NH;

    extern __shared__ __half shh[];
    __half* qs = shh;
    __half* ks = qs + AROWS * AQ_STR;
    __half* vs = ks + AROWS * AQ_STR;

    const int tid  = threadIdx.x;
    const int warp = tid >> 5;
    const int lane = tid & 31;
    const float scale = 0.1767766952966369f;   // 1/sqrt(32)

    const __half* base = QKV + (size_t)wi * NTOK * (3 * DIM) + hdi * HD;
    for (int idx = tid; idx < AROWS * 4; idx += 128) {
        const int row = idx >> 2, c = idx & 3;
        uint4 q = make_uint4(0, 0, 0, 0), k = q, v = q;
        if (row < NTOK) {
            const __half* src = base + (size_t)row * (3 * DIM) + c * 8;
            q = *(const uint4*)(src);
            k = *(const uint4*)(src + DIM);
            v = *(const uint4*)(src + 2 * DIM);
        }
        *(uint4*)(qs + row * AQ_STR + c * 8) = q;
        *(uint4*)(ks + row * AQ_STR + c * 8) = k;
        *(uint4*)(vs + row * AQ_STR + c * 8) = v;
    }
    __syncthreads();

    const uint32_t qb = smem_u32(qs);
    const uint32_t kb = smem_u32(ks);
    const uint32_t vb = smem_u32(vs);

    const int g  = lane >> 3;
    const int r8 = lane & 7;
    const int a_row_off = (g & 1) * 8 + r8;
    const int a_cg      = (g >> 1) * 16;
    const int b_row_off = (g >> 1) * 8 + r8;
    const int b_cg      = (g & 1) * 16;

    const int rq  = lane >> 2;
    const int cq2 = (lane & 3) * 2;

    for (int t = warp; t < 13; t += 4) {
        const int m0 = t * 16;

        uint32_t af[2][4];
#pragma unroll
        for (int s = 0; s < 2; s++)
            ldsm_x4(af[s], qb + (uint32_t)((m0 + a_row_off) * 80 + a_cg + s * 32));

        float c[26][4];
#pragma unroll
        for (int nt = 0; nt < 26; nt++) { c[nt][0] = c[nt][1] = c[nt][2] = c[nt][3] = 0.f; }
#pragma unroll
        for (int np = 0; np < 13; np++) {
#pragma unroll
            for (int s = 0; s < 2; s++) {
                uint32_t bf[4];
                ldsm_x4(bf, kb + (uint32_t)((np * 16 + b_row_off) * 80 + b_cg + s * 32));
                mma_f16(c[2 * np],     af[s], &bf[0]);
                mma_f16(c[2 * np + 1], af[s], &bf[2]);
            }
        }

        float mx0 = -1e30f, mx1 = -1e30f;
#pragma unroll
        for (int nt = 0; nt < 26; nt++) {
            const int col = nt * 8 + cq2;
            if (col < NTOK)     { mx0 = fmaxf(mx0, c[nt][0]); mx1 = fmaxf(mx1, c[nt][2]); }
            if (col + 1 < NTOK) { mx0 = fmaxf(mx0, c[nt][1]); mx1 = fmaxf(mx1, c[nt][3]); }
        }
        mx0 = fmaxf(mx0, __shfl_xor_sync(0xffffffffu, mx0, 1));
        mx0 = fmaxf(mx0, __shfl_xor_sync(0xffffffffu, mx0, 2));
        mx1 = fmaxf(mx1, __shfl_xor_sync(0xffffffffu, mx1, 1));
        mx1 = fmaxf(mx1, __shfl_xor_sync(0xffffffffu, mx1, 2));

        uint32_t ph[26][2];
        float sum0 = 0.f, sum1 = 0.f;
#pragma unroll
        for (int nt = 0; nt < 26; nt++) {
            const int col = nt * 8 + cq2;
            float p0 = (col < NTOK)     ? __expf((c[nt][0] - mx0) * scale) : 0.f;
            float p1 = (col + 1 < NTOK) ? __expf((c[nt][1] - mx0) * scale) : 0.f;
            float p2 = (col < NTOK)     ? __expf((c[nt][2] - mx1) * scale) : 0.f;
            float p3 = (col + 1 < NTOK) ? __expf((c[nt][3] - mx1) * scale) : 0.f;
            sum0 += p0 + p1;
            sum1 += p2 + p3;
            ph[nt][0] = pack_h2(p0, p1);
            ph[nt][1] = pack_h2(p2, p3);
        }
        sum0 += __shfl_xor_sync(0xffffffffu, sum0, 1);
        sum0 += __shfl_xor_sync(0xffffffffu, sum0, 2);
        sum1 += __shfl_xor_sync(0xffffffffu, sum1, 1);
        sum1 += __shfl_xor_sync(0xffffffffu, sum1, 2);

        float o[4][4];
#pragma unroll
        for (int n = 0; n < 4; n++) { o[n][0] = o[n][1] = o[n][2] = o[n][3] = 0.f; }
#pragma unroll
        for (int kt = 0; kt < 13; kt++) {
            uint32_t a[4] = { ph[2 * kt][0], ph[2 * kt][1],
                              ph[2 * kt + 1][0], ph[2 * kt + 1][1] };
            uint32_t v0f[4], v1f[4];
            ldsm_x4_t(v0f, vb + (uint32_t)((kt * 16 + a_row_off) * 80 + a_cg));
            ldsm_x4_t(v1f, vb + (uint32_t)((kt * 16 + a_row_off) * 80 + a_cg + 32));
            mma_f16(o[0], a, &v0f[0]);
            mma_f16(o[1], a, &v0f[2]);
            mma_f16(o[2], a, &v1f[0]);
            mma_f16(o[3], a, &v1f[2]);
        }

        const float inv0 = 1.0f / sum0;
        const float inv1 = 1.0f / sum1;
        const int r0 = m0 + rq, r1 = m0 + rq + 8;
#pragma unroll
        for (int n = 0; n < 4; n++) {
            const int col = hdi * HD + n * 8 + cq2;
            if (r0 < NTOK)
                *(__half2*)(ATT + ((size_t)wi * NTOK + r0) * DIM + col) =
                    __halves2half2(__float2half_rn(o[n][0] * inv0), __float2half_rn(o[n][1] * inv0));
            if (r1 < NTOK)
                *(__half2*)(ATT + ((size_t)wi * NTOK + r1) * DIM + col) =
                    __halves2half2(__float2half_rn(o[n][2] * inv1), __float2half_rn(o[n][3] * inv1));
        }
    }
}

// ---------------------------------------------------------------------------
// 5) Windowed (wi,n,c) -> BCHW output
// ---------------------------------------------------------------------------
__global__ void unwin_kernel(const float* __restrict__ X,
                             float* __restrict__ out)
{
    const int ct = blockIdx.x >> 1, wt = blockIdx.x & 1;
    const int h = blockIdx.y, b = blockIdx.z;
    const int c0 = ct * 32, w0 = wt * 32;

    __shared__ float sm[32][33];
    const int tx = threadIdx.x, ty = threadIdx.y;

#pragma unroll
    for (int k = 0; k < 4; k++) {
        int r = ty + 8 * k;
        int w = w0 + r;
        if (w < WW) {
            int wi = (b * 4 + h / WS) * 4 + w / WS;
            int n  = (h % WS) * WS + (w % WS);
            sm[r][tx] = X[((size_t)wi * NTOK + n) * DIM + c0 + tx];
        }
    }
    __syncthreads();

#pragma unroll
    for (int k = 0; k < 4; k++) {
        int c = c0 + ty + 8 * k;
        int w = w0 + tx;
        if (w < WW)
            out[(((size_t)b * DIM + c) * HH + h) * WW + w] = sm[tx][ty + 8 * k];
    }
}

// ---------------------------------------------------------------------------
// Launch
// ---------------------------------------------------------------------------
extern "C" void kernel_launch(void* const* d_in, const int* in_sizes, int n_in,
                              void* d_out, int out_size)
{
    const float* x      = (const float*)d_in[0];
    const float* conv_w = (const float*)d_in[1];
    const float* conv_b = (const float*)d_in[2];
    const float* ln1_g  = (const float*)d_in[3];
    const float* ln1_b  = (const float*)d_in[4];
    const float* qkv_w  = (const float*)d_in[5];
    const float* qkv_b  = (const float*)d_in[6];
    const float* proj_w = (const float*)d_in[7];
    const float* proj_b = (const float*)d_in[8];
    const float* ln2_g  = (const float*)d_in[9];
    const float* ln2_b  = (const float*)d_in[10];
    const float* fc1_w  = (const float*)d_in[11];
    const float* fc1_b  = (const float*)d_in[12];
    const float* fc2_w  = (const float*)d_in[13];
    const float* fc2_b  = (const float*)d_in[14];
    float* out = (float*)d_out;

    float *X0, *X1;
    __half *Y, *QKV, *ATT, *F, *Wh;
    cudaGetSymbolAddress((void**)&X0,  g_X0);
    cudaGetSymbolAddress((void**)&Y,   g_Y);
    cudaGetSymbolAddress((void**)&QKV, g_QKV);
    cudaGetSymbolAddress((void**)&ATT, g_ATT);
    cudaGetSymbolAddress((void**)&X1,  g_X1);
    cudaGetSymbolAddress((void**)&F,   g_F);
    cudaGetSymbolAddress((void**)&Wh,  g_Wh);

    cudaFuncSetAttribute(attn_h_kernel, cudaFuncAttributeMaxDynamicSharedMemorySize, ATTN_SMEM);
    cudaFuncSetAttribute(hgemm_kernel, cudaFuncAttributeMaxDynamicSharedMemorySize, GEMM_SMEM);

    // 0) fp16 weights (single launch)
    cvtw_all_kernel<<<(1769472 + 255) / 256, 256>>>(qkv_w, proj_w, fc1_w, fc2_w, Wh);

    // 1) conv PE + residual -> X0
    conv_pe_kernel<<<dim3(DIM / 8, HH, BATCH), dim3(8, 56)>>>(x, conv_w, conv_b, X0);

    // 2) LN1 -> Y (fp16)
    ln_kernel<<<TOK / 8, 256>>>(X0, ln1_g, ln1_b, Y);

    // 3) QKV GEMM (fp16 in, fp16 out)
    hgemm_kernel<<<dim3(3 * DIM / BN, TOK / BM), 256, GEMM_SMEM>>>(
        Y, Wh + WOFF_QKV, qkv_b, nullptr, nullptr, QKV, TOK, 3 * DIM, DIM, 0);

    // 4) window attention -> ATT (fp16)
    attn_h_kernel<<<NWIN * NH, 128, ATTN_SMEM>>>(QKV, ATT);

    // 5) proj GEMM + residual(X0) -> X1 (fp32)
    hgemm_kernel<<<dim3(DIM / BN, TOK / BM), 256, GEMM_SMEM>>>(
        ATT, Wh + WOFF_PROJ, proj_b, X0, X1, nullptr, TOK, DIM, DIM, 0);

    // 6) LN2 -> Y (fp16)
    ln_kernel<<<TOK / 8, 256>>>(X1, ln2_g, ln2_b, Y);

    // 7) FC1 GEMM + GELU -> F (fp16)
    hgemm_kernel<<<dim3(4 * DIM / BN, TOK / BM), 256, GEMM_SMEM>>>(
        Y, Wh + WOFF_FC1, fc1_b, nullptr, nullptr, F, TOK, 4 * DIM, DIM, 1);

    // 8) FC2 GEMM + residual(X1) -> X0 (fp32)
    hgemm_kernel<<<dim3(DIM / BN, TOK / BM), 256, GEMM_SMEM>>>(
        F, Wh + WOFF_FC2, fc2_b, X1, X0, nullptr, TOK, DIM, 4 * DIM, 0);

    // 9) un-window -> BCHW
    unwin_kernel<<<dim3(24, HH, BATCH), dim3(32, 8)>>>(X0, out);
}

// round 10
// speedup vs baseline: 1.1207x; 1.0751x over previous
#include <cuda_runtime.h>
#include <cuda_bf16.h>
#include <cuda_fp16.h>
#include <math.h>
#include <cstdint>

// ---------------------------------------------------------------------------
// Problem constants
// ---------------------------------------------------------------------------
#define DIM   384
#define NH    12
#define HD    32
#define WS    14
#define BATCH 16
#define HH    56
#define WW    56
#define NWIN  256
#define NTOK  196
#define TOK   50176          // NWIN*NTOK

// ---------------------------------------------------------------------------
// Scratch
// ---------------------------------------------------------------------------
__device__ __align__(16) float  g_X0 [(size_t)TOK * DIM];
__device__ __align__(16) __half g_Y  [(size_t)TOK * DIM];
__device__ __align__(16) __half g_QKV[(size_t)TOK * 3 * DIM];
__device__ __align__(16) __half g_ATT[(size_t)TOK * DIM];
__device__ __align__(16) float  g_X1 [(size_t)TOK * DIM];
__device__ __align__(16) __half g_F  [(size_t)TOK * 4 * DIM];
__device__ __align__(16) __half g_Wh [1769472];          // fp16 weights

#define N_QKV  (3 * DIM * DIM)
#define N_PROJ (DIM * DIM)
#define N_FC   (4 * DIM * DIM)
#define WOFF_QKV  0
#define WOFF_PROJ N_QKV
#define WOFF_FC1  (WOFF_PROJ + N_PROJ)
#define WOFF_FC2  (WOFF_FC1 + N_FC)

// ---------------------------------------------------------------------------
// helpers
// ---------------------------------------------------------------------------
__device__ __forceinline__ uint32_t smem_u32(const void* p) {
    uint32_t a;
    asm("{ .reg .u64 t; cvta.to.shared.u64 t, %1; cvt.u32.u64 %0, t; }" : "=r"(a) : "l"(p));
    return a;
}
__device__ __forceinline__ void cp16(uint32_t dst, const void* src) {
    asm volatile("cp.async.cg.shared.global [%0], [%1], 16;" :: "r"(dst), "l"(src));
}
#define CP_COMMIT() asm volatile("cp.async.commit_group;" ::: "memory")
#define CP_WAIT1()  asm volatile("cp.async.wait_group 1;" ::: "memory")

__device__ __forceinline__ void ldsm_x4(uint32_t* r, uint32_t a) {
    asm volatile("ldmatrix.sync.aligned.m8n8.x4.shared.b16 {%0,%1,%2,%3}, [%4];"
                 : "=r"(r[0]), "=r"(r[1]), "=r"(r[2]), "=r"(r[3]) : "r"(a));
}
__device__ __forceinline__ void ldsm_x4_t(uint32_t* r, uint32_t a) {
    asm volatile("ldmatrix.sync.aligned.m8n8.x4.trans.shared.b16 {%0,%1,%2,%3}, [%4];"
                 : "=r"(r[0]), "=r"(r[1]), "=r"(r[2]), "=r"(r[3]) : "r"(a));
}
__device__ __forceinline__ void mma_f16(float* d, const uint32_t* a, const uint32_t* b) {
    asm volatile(
        "mma.sync.aligned.m16n8k16.row.col.f32.f16.f16.f32 "
        "{%0,%1,%2,%3}, {%4,%5,%6,%7}, {%8,%9}, {%0,%1,%2,%3};"
        : "+f"(d[0]), "+f"(d[1]), "+f"(d[2]), "+f"(d[3])
        : "r"(a[0]), "r"(a[1]), "r"(a[2]), "r"(a[3]), "r"(b[0]), "r"(b[1]));
}
__device__ __forceinline__ uint32_t pack_h2(float x, float y) {
    __half2 h = __floats2half2_rn(x, y);
    return *reinterpret_cast<uint32_t*>(&h);
}

// ---------------------------------------------------------------------------
// 0) all four weight conversions in ONE launch
// ---------------------------------------------------------------------------
__global__ void cvtw_all_kernel(const float* __restrict__ qkv_w,
                                const float* __restrict__ proj_w,
                                const float* __restrict__ fc1_w,
                                const float* __restrict__ fc2_w,
                                __half* __restrict__ dst)
{
    int i = blockIdx.x * blockDim.x + threadIdx.x;
    if (i >= 1769472) return;
    float v;
    if (i < WOFF_PROJ)                v = qkv_w[i];
    else if (i < WOFF_FC1)            v = proj_w[i - WOFF_PROJ];
    else if (i < WOFF_FC2)            v = fc1_w[i - WOFF_FC1];
    else                              v = fc2_w[i - WOFF_FC2];
    dst[i] = __float2half_rn(v);
}

// ---------------------------------------------------------------------------
// 1) depthwise 3x3 conv PE + residual -> windowed (wi,n,c)
// ---------------------------------------------------------------------------
__global__ void conv_pe_kernel(const float* __restrict__ x,
                               const float* __restrict__ cw,
                               const float* __restrict__ cb,
                               float* __restrict__ X0)
{
    const int cg = blockIdx.x * 8;
    const int h  = blockIdx.y;
    const int b  = blockIdx.z;

    __shared__ float sm[8][3][58];

    const int tid = threadIdx.y * 8 + threadIdx.x;
    const int lc  = tid / 56;
    const int lw  = tid % 56;

    const float* xp = x + ((size_t)(b * DIM + cg + lc) * HH) * WW;
#pragma unroll
    for (int r = 0; r < 3; r++) {
        int hh = h - 1 + r;
        float v = (hh >= 0 && hh < HH) ? xp[hh * WW + lw] : 0.0f;
        sm[lc][r][lw + 1] = v;
        if (lw == 0)  sm[lc][r][0]  = 0.0f;
        if (lw == 55) sm[lc][r][57] = 0.0f;
    }
    __syncthreads();

    const int c = threadIdx.x;
    const int w = threadIdx.y;

    float wreg[9];
    const float* cwp = cw + (size_t)(cg + c) * 9;
#pragma unroll
    for (int i = 0; i < 9; i++) wreg[i] = cwp[i];

    float pe = 0.0f;
#pragma unroll
    for (int kh = 0; kh < 3; kh++)
#pragma unroll
        for (int kw = 0; kw < 3; kw++)
            pe += wreg[kh * 3 + kw] * sm[c][kh][w + kw];

    float val = sm[c][1][w + 1] + pe + cb[cg + c];

    const int wi = (b * 4 + h / WS) * 4 + (w / WS);
    const int n  = (h % WS) * WS + (w % WS);
    X0[((size_t)wi * NTOK + n) * DIM + cg + c] = val;
}

// ---------------------------------------------------------------------------
// 2) LayerNorm; fp16 output (GEMM A operand)
// ---------------------------------------------------------------------------
__global__ void ln_kernel(const float* __restrict__ X,
                          const float* __restrict__ gamma,
                          const float* __restrict__ beta,
                          __half* __restrict__ Y)
{
    const int warp = (blockIdx.x * blockDim.x + threadIdx.x) >> 5;
    const int lane = threadIdx.x & 31;
    if (warp >= TOK) return;

    const float* xp = X + (size_t)warp * DIM;
    float v[12];
    float s = 0.0f;
#pragma unroll
    for (int k = 0; k < 12; k++) { v[k] = xp[lane + 32 * k]; s += v[k]; }
#pragma unroll
    for (int o = 16; o; o >>= 1) s += __shfl_xor_sync(0xffffffffu, s, o);
    const float mean = s * (1.0f / DIM);

    float q = 0.0f;
#pragma unroll
    for (int k = 0; k < 12; k++) { float d = v[k] - mean; q += d * d; }
#pragma unroll
    for (int o = 16; o; o >>= 1) q += __shfl_xor_sync(0xffffffffu, q, o);
    const float inv = rsqrtf(q * (1.0f / DIM) + 1e-5f);

    __half* yp = Y + (size_t)warp * DIM;
#pragma unroll
    for (int k = 0; k < 12; k++) {
        int c = lane + 32 * k;
        yp[c] = __float2half_rn((v[k] - mean) * inv * gamma[c] + beta[c]);
    }
}

// ---------------------------------------------------------------------------
// 3) FP16 mma.sync GEMM: C[M,N] = act(A[M,K] @ W[N,K]^T + bias) (+ R)
//    CTA 128x128, BK=64, 8 warps (2m x 4n), warp 64x32.  [R7 config: best]
//    3-stage cp.async (110.6KB) -> 2 CTAs/SM (16 warps/SM). 144B odd rows.
// ---------------------------------------------------------------------------
#define BM 128
#define BN 128
#define BK 64
#define ROW_B 144                            // 9 granules, odd -> conflict-free
#define A_BYTES (128 * ROW_B)                // 18432
#define STAGE_B (2 * A_BYTES)                // 36864
#define NSTAGE  3
#define GEMM_SMEM (NSTAGE * STAGE_B)         // 110592

__global__ __launch_bounds__(256, 2)
void hgemm_kernel(const __half* __restrict__ A,
                  const __half* __restrict__ W,
                  const float* __restrict__ bias,
                  const float* __restrict__ R,
                  float* __restrict__ Cf,
                  __half* __restrict__ Ch,
                  int M, int N, int K, int act)
{
    extern __shared__ char smc[];
    const uint32_t smem_base = smem_u32(smc);
    const int tid  = threadIdx.x;
    const int lane = tid & 31;
    const int wid  = tid >> 5;
    const int bm = blockIdx.y * BM;
    const int bn = blockIdx.x * BN;

    const int warp_m = (wid & 1) * 64;
    const int warp_n = (wid >> 1) * 32;

    float acc[4][4][4];
#pragma unroll
    for (int im = 0; im < 4; im++)
#pragma unroll
        for (int in = 0; in < 4; in++)
#pragma unroll
            for (int j = 0; j < 4; j++) acc[im][in][j] = 0.0f;

    // ldmatrix lane geometry
    const int g  = lane >> 3;
    const int r8 = lane & 7;
    const int a_row = warp_m + (g & 1) * 8 + r8;     // + im*16
    const int a_cg  = g >> 1;                        // 16B chunk within k16
    const int b_row = warp_n + (g >> 1) * 8 + r8;    // + inp*16
    const int b_cg  = g & 1;

    const int NC = K >> 6;

    // fill: thread t -> row t>>1 (A and B), chunk quad (t&1)*4
    const int fr  = tid >> 1;
    const int fc0 = (tid & 1) * 4;
    auto fill = [&](int kc, int st) {
        const int k0 = kc << 6;
        const uint32_t sb = smem_base + (uint32_t)st * STAGE_B;
        const __half* Ag = A + (size_t)(bm + fr) * K + k0;
        const __half* Wg = W + (size_t)(bn + fr) * K + k0;
#pragma unroll
        for (int c = 0; c < 4; c++) {
            const int cc = fc0 + c;
            const uint32_t so = (uint32_t)(fr * ROW_B + cc * 16);
            cp16(sb + so, Ag + cc * 8);
            cp16(sb + A_BYTES + so, Wg + cc * 8);
        }
    };

    fill(0, 0); CP_COMMIT();
    fill(1, 1); CP_COMMIT();

    for (int kc = 0; kc < NC; kc++) {
        CP_WAIT1();
        __syncthreads();

        if (kc + 2 < NC) fill(kc + 2, (kc + 2) % NSTAGE);
        CP_COMMIT();                      // unconditional: constant depth

        const uint32_t ab = smem_base + (uint32_t)(kc % NSTAGE) * STAGE_B;
        const uint32_t bb = ab + A_BYTES;

#pragma unroll
        for (int s = 0; s < 4; s++) {
            uint32_t af[4][4], bf[2][4];
#pragma unroll
            for (int im = 0; im < 4; im++)
                ldsm_x4(af[im], ab + (uint32_t)((a_row + im * 16) * ROW_B +
                                                (s * 2 + a_cg) * 16));
#pragma unroll
            for (int inp = 0; inp < 2; inp++)
                ldsm_x4(bf[inp], bb + (uint32_t)((b_row + inp * 16) * ROW_B +
                                                 (s * 2 + b_cg) * 16));
#pragma unroll
            for (int im = 0; im < 4; im++)
#pragma unroll
                for (int in = 0; in < 4; in++)
                    mma_f16(acc[im][in], af[im], &bf[in >> 1][(in & 1) * 2]);
        }
    }

    // epilogue
    const int rq = lane >> 2;
    const int cq = (lane & 3) * 2;
#pragma unroll
    for (int im = 0; im < 4; im++) {
        const int row0 = bm + warp_m + im * 16 + rq;
#pragma unroll
        for (int in = 0; in < 4; in++) {
            const int col = bn + warp_n + in * 8 + cq;
            const float2 bv = *(const float2*)(bias + col);
            float v0 = acc[im][in][0] + bv.x;
            float v1 = acc[im][in][1] + bv.y;
            float v2 = acc[im][in][2] + bv.x;
            float v3 = acc[im][in][3] + bv.y;
            if (act == 1) {
                v0 = 0.5f * v0 * (1.0f + erff(v0 * 0.70710678118654752f));
                v1 = 0.5f * v1 * (1.0f + erff(v1 * 0.70710678118654752f));
                v2 = 0.5f * v2 * (1.0f + erff(v2 * 0.70710678118654752f));
                v3 = 0.5f * v3 * (1.0f + erff(v3 * 0.70710678118654752f));
            }
            if (Ch) {
                *(__half2*)(Ch + (size_t)row0 * N + col) =
                    __halves2half2(__float2half_rn(v0), __float2half_rn(v1));
                *(__half2*)(Ch + (size_t)(row0 + 8) * N + col) =
                    __halves2half2(__float2half_rn(v2), __float2half_rn(v3));
            } else {
                if (R) {
                    const float2 r0 = *(const float2*)(R + (size_t)row0 * N + col);
                    const float2 r1 = *(const float2*)(R + (size_t)(row0 + 8) * N + col);
                    v0 += r0.x; v1 += r0.y; v2 += r1.x; v3 += r1.y;
                }
                *(float2*)(Cf + (size_t)row0 * N + col)       = make_float2(v0, v1);
                *(float2*)(Cf + (size_t)(row0 + 8) * N + col) = make_float2(v2, v3);
            }
        }
    }
}

// ---------------------------------------------------------------------------
// 4) Window attention, full fp16 mma. 128 threads (4 warps), occupancy 2.
//    S accumulators repack DIRECTLY into PV A-fragments (no P smem).
// ---------------------------------------------------------------------------
#define AQ_STR 40
#define AROWS  208
#define ATTN_SMEM (3 * AROWS * AQ_STR * 2)      // 49920 B

__global__ __launch_bounds__(128, 2)
void attn_h_kernel(const __half* __restrict__ QKV, __half* __restrict__ ATT)
{
    const int wi  = blockIdx.x / NH;
    const int hdi = blockIdx.x % NH;

    extern __shared__ __half shh[];
    __half* qs = shh;
    __half* ks = qs + AROWS * AQ_STR;
    __half* vs = ks + AROWS * AQ_STR;

    const int tid  = threadIdx.x;
    const int warp = tid >> 5;
    const int lane = tid & 31;
    const float scale = 0.1767766952966369f;   // 1/sqrt(32)

    const __half* base = QKV + (size_t)wi * NTOK * (3 * DIM) + hdi * HD;
    for (int idx = tid; idx < AROWS * 4; idx += 128) {
        const int row = idx >> 2, c = idx & 3;
        uint4 q = make_uint4(0, 0, 0, 0), k = q, v = q;
        if (row < NTOK) {
            const __half* src = base + (size_t)row * (3 * DIM) + c * 8;
            q = *(const uint4*)(src);
            k = *(const uint4*)(src + DIM);
            v = *(const uint4*)(src + 2 * DIM);
        }
        *(uint4*)(qs + row * AQ_STR + c * 8) = q;
        *(uint4*)(ks + row * AQ_STR + c * 8) = k;
        *(uint4*)(vs + row * AQ_STR + c * 8) = v;
    }
    __syncthreads();

    const uint32_t qb = smem_u32(qs);
    const uint32_t kb = smem_u32(ks);
    const uint32_t vb = smem_u32(vs);

    const int g  = lane >> 3;
    const int r8 = lane & 7;
    const int a_row_off = (g & 1) * 8 + r8;
    const int a_cg      = (g >> 1) * 16;
    const int b_row_off = (g >> 1) * 8 + r8;
    const int b_cg      = (g & 1) * 16;

    const int rq  = lane >> 2;
    const int cq2 = (lane & 3) * 2;

    for (int t = warp; t < 13; t += 4) {
        const int m0 = t * 16;

        uint32_t af[2][4];
#pragma unroll
        for (int s = 0; s < 2; s++)
            ldsm_x4(af[s], qb + (uint32_t)((m0 + a_row_off) * 80 + a_cg + s * 32));

        float c[26][4];
#pragma unroll
        for (int nt = 0; nt < 26; nt++) { c[nt][0] = c[nt][1] = c[nt][2] = c[nt][3] = 0.f; }
#pragma unroll
        for (int np = 0; np < 13; np++) {
#pragma unroll
            for (int s = 0; s < 2; s++) {
                uint32_t bf[4];
                ldsm_x4(bf, kb + (uint32_t)((np * 16 + b_row_off) * 80 + b_cg + s * 32));
                mma_f16(c[2 * np],     af[s], &bf[0]);
                mma_f16(c[2 * np + 1], af[s], &bf[2]);
            }
        }

        float mx0 = -1e30f, mx1 = -1e30f;
#pragma unroll
        for (int nt = 0; nt < 26; nt++) {
            const int col = nt * 8 + cq2;
            if (col < NTOK)     { mx0 = fmaxf(mx0, c[nt][0]); mx1 = fmaxf(mx1, c[nt][2]); }
            if (col + 1 < NTOK) { mx0 = fmaxf(mx0, c[nt][1]); mx1 = fmaxf(mx1, c[nt][3]); }
        }
        mx0 = fmaxf(mx0, __shfl_xor_sync(0xffffffffu, mx0, 1));
        mx0 = fmaxf(mx0, __shfl_xor_sync(0xffffffffu, mx0, 2));
        mx1 = fmaxf(mx1, __shfl_xor_sync(0xffffffffu, mx1, 1));
        mx1 = fmaxf(mx1, __shfl_xor_sync(0xffffffffu, mx1, 2));

        uint32_t ph[26][2];
        float sum0 = 0.f, sum1 = 0.f;
#pragma unroll
        for (int nt = 0; nt < 26; nt++) {
            const int col = nt * 8 + cq2;
            float p0 = (col < NTOK)     ? __expf((c[nt][0] - mx0) * scale) : 0.f;
            float p1 = (col + 1 < NTOK) ? __expf((c[nt][1] - mx0) * scale) : 0.f;
            float p2 = (col < NTOK)     ? __expf((c[nt][2] - mx1) * scale) : 0.f;
            float p3 = (col + 1 < NTOK) ? __expf((c[nt][3] - mx1) * scale) : 0.f;
            sum0 += p0 + p1;
            sum1 += p2 + p3;
            ph[nt][0] = pack_h2(p0, p1);
            ph[nt][1] = pack_h2(p2, p3);
        }
        sum0 += __shfl_xor_sync(0xffffffffu, sum0, 1);
        sum0 += __shfl_xor_sync(0xffffffffu, sum0, 2);
        sum1 += __shfl_xor_sync(0xffffffffu, sum1, 1);
        sum1 += __shfl_xor_sync(0xffffffffu, sum1, 2);

        float o[4][4];
#pragma unroll
        for (int n = 0; n < 4; n++) { o[n][0] = o[n][1] = o[n][2] = o[n][3] = 0.f; }
#pragma unroll
        for (int kt = 0; kt < 13; kt++) {
            uint32_t a[4] = { ph[2 * kt][0], ph[2 * kt][1],
                              ph[2 * kt + 1][0], ph[2 * kt + 1][1] };
            uint32_t v0f[4], v1f[4];
            ldsm_x4_t(v0f, vb + (uint32_t)((kt * 16 + a_row_off) * 80 + a_cg));
            ldsm_x4_t(v1f, vb + (uint32_t)((kt * 16 + a_row_off) * 80 + a_cg + 32));
            mma_f16(o[0], a, &v0f[0]);
            mma_f16(o[1], a, &v0f[2]);
            mma_f16(o[2], a, &v1f[0]);
            mma_f16(o[3], a, &v1f[2]);
        }

        const float inv0 = 1.0f / sum0;
        const float inv1 = 1.0f / sum1;
        const int r0 = m0 + rq, r1 = m0 + rq + 8;
#pragma unroll
        for (int n = 0; n < 4; n++) {
            const int col = hdi * HD + n * 8 + cq2;
            if (r0 < NTOK)
                *(__half2*)(ATT + ((size_t)wi * NTOK + r0) * DIM + col) =
                    __halves2half2(__float2half_rn(o[n][0] * inv0), __float2half_rn(o[n][1] * inv0));
            if (r1 < NTOK)
                *(__half2*)(ATT + ((size_t)wi * NTOK + r1) * DIM + col) =
                    __halves2half2(__float2half_rn(o[n][2] * inv1), __float2half_rn(o[n][3] * inv1));
        }
    }
}

// ---------------------------------------------------------------------------
// 5) Windowed (wi,n,c) -> BCHW output
// ---------------------------------------------------------------------------
__global__ void unwin_kernel(const float* __restrict__ X,
                             float* __restrict__ out)
{
    const int ct = blockIdx.x >> 1, wt = blockIdx.x & 1;
    const int h = blockIdx.y, b = blockIdx.z;
    const int c0 = ct * 32, w0 = wt * 32;

    __shared__ float sm[32][33];
    const int tx = threadIdx.x, ty = threadIdx.y;

#pragma unroll
    for (int k = 0; k < 4; k++) {
        int r = ty + 8 * k;
        int w = w0 + r;
        if (w < WW) {
            int wi = (b * 4 + h / WS) * 4 + w / WS;
            int n  = (h % WS) * WS + (w % WS);
            sm[r][tx] = X[((size_t)wi * NTOK + n) * DIM + c0 + tx];
        }
    }
    __syncthreads();

#pragma unroll
    for (int k = 0; k < 4; k++) {
        int c = c0 + ty + 8 * k;
        int w = w0 + tx;
        if (w < WW)
            out[(((size_t)b * DIM + c) * HH + h) * WW + w] = sm[tx][ty + 8 * k];
    }
}

// ---------------------------------------------------------------------------
// Launch
// ---------------------------------------------------------------------------
extern "C" void kernel_launch(void* const* d_in, const int* in_sizes, int n_in,
                              void* d_out, int out_size)
{
    const float* x      = (const float*)d_in[0];
    const float* conv_w = (const float*)d_in[1];
    const float* conv_b = (const float*)d_in[2];
    const float* ln1_g  = (const float*)d_in[3];
    const float* ln1_b  = (const float*)d_in[4];
    const float* qkv_w  = (const float*)d_in[5];
    const float* qkv_b  = (const float*)d_in[6];
    const float* proj_w = (const float*)d_in[7];
    const float* proj_b = (const float*)d_in[8];
    const float* ln2_g  = (const float*)d_in[9];
    const float* ln2_b  = (const float*)d_in[10];
    const float* fc1_w  = (const float*)d_in[11];
    const float* fc1_b  = (const float*)d_in[12];
    const float* fc2_w  = (const float*)d_in[13];
    const float* fc2_b  = (const float*)d_in[14];
    float* out = (float*)d_out;

    float *X0, *X1;
    __half *Y, *QKV, *ATT, *F, *Wh;
    cudaGetSymbolAddress((void**)&X0,  g_X0);
    cudaGetSymbolAddress((void**)&Y,   g_Y);
    cudaGetSymbolAddress((void**)&QKV, g_QKV);
    cudaGetSymbolAddress((void**)&ATT, g_ATT);
    cudaGetSymbolAddress((void**)&X1,  g_X1);
    cudaGetSymbolAddress((void**)&F,   g_F);
    cudaGetSymbolAddress((void**)&Wh,  g_Wh);

    cudaFuncSetAttribute(attn_h_kernel, cudaFuncAttributeMaxDynamicSharedMemorySize, ATTN_SMEM);
    cudaFuncSetAttribute(hgemm_kernel, cudaFuncAttributeMaxDynamicSharedMemorySize, GEMM_SMEM);

    // 0) fp16 weights (single launch)
    cvtw_all_kernel<<<(1769472 + 255) / 256, 256>>>(qkv_w, proj_w, fc1_w, fc2_w, Wh);

    // 1) conv PE + residual -> X0
    conv_pe_kernel<<<dim3(DIM / 8, HH, BATCH), dim3(8, 56)>>>(x, conv_w, conv_b, X0);

    // 2) LN1 -> Y (fp16)
    ln_kernel<<<TOK / 8, 256>>>(X0, ln1_g, ln1_b, Y);

    // 3) QKV GEMM (fp16 in, fp16 out)
    hgemm_kernel<<<dim3(3 * DIM / BN, TOK / BM), 256, GEMM_SMEM>>>(
        Y, Wh + WOFF_QKV, qkv_b, nullptr, nullptr, QKV, TOK, 3 * DIM, DIM, 0);

    // 4) window attention -> ATT (fp16)
    attn_h_kernel<<<NWIN * NH, 128, ATTN_SMEM>>>(QKV, ATT);

    // 5) proj GEMM + residual(X0) -> X1 (fp32)
    hgemm_kernel<<<dim3(DIM / BN, TOK / BM), 256, GEMM_SMEM>>>(
        ATT, Wh + WOFF_PROJ, proj_b, X0, X1, nullptr, TOK, DIM, DIM, 0);

    // 6) LN2 -> Y (fp16)
    ln_kernel<<<TOK / 8, 256>>>(X1, ln2_g, ln2_b, Y);

    // 7) FC1 GEMM + GELU -> F (fp16)
    hgemm_kernel<<<dim3(4 * DIM / BN, TOK / BM), 256, GEMM_SMEM>>>(
        Y, Wh + WOFF_FC1, fc1_b, nullptr, nullptr, F, TOK, 4 * DIM, DIM, 1);

    // 8) FC2 GEMM + residual(X1) -> X0 (fp32)
    hgemm_kernel<<<dim3(DIM / BN, TOK / BM), 256, GEMM_SMEM>>>(
        F, Wh + WOFF_FC2, fc2_b, X1, X0, nullptr, TOK, DIM, 4 * DIM, 0);

    // 9) un-window -> BCHW
    unwin_kernel<<<dim3(24, HH, BATCH), dim3(32, 8)>>>(X0, out);
}

// round 11
// speedup vs baseline: 1.2850x; 1.1466x over previous
#include <cuda_runtime.h>
#include <cuda_bf16.h>
#include <cuda_fp16.h>
#include <math.h>
#include <cstdint>

// ---------------------------------------------------------------------------
// Problem constants
// ---------------------------------------------------------------------------
#define DIM   384
#define NH    12
#define HD    32
#define WS    14
#define BATCH 16
#define HH    56
#define WW    56
#define NWIN  256
#define NTOK  196
#define TOK   50176          // NWIN*NTOK

// ---------------------------------------------------------------------------
// Scratch
// ---------------------------------------------------------------------------
__device__ __align__(16) float  g_X0 [(size_t)TOK * DIM];
__device__ __align__(16) __half g_Y  [(size_t)TOK * DIM];
__device__ __align__(16) __half g_QKV[(size_t)TOK * 3 * DIM];
__device__ __align__(16) __half g_ATT[(size_t)TOK * DIM];
__device__ __align__(16) float  g_X1 [(size_t)TOK * DIM];
__device__ __align__(16) __half g_F  [(size_t)TOK * 4 * DIM];
__device__ __align__(16) __half g_Wh [1769472];          // fp16 weights

#define N_QKV  (3 * DIM * DIM)
#define N_PROJ (DIM * DIM)
#define N_FC   (4 * DIM * DIM)
#define WOFF_QKV  0
#define WOFF_PROJ N_QKV
#define WOFF_FC1  (WOFF_PROJ + N_PROJ)
#define WOFF_FC2  (WOFF_FC1 + N_FC)

// ---------------------------------------------------------------------------
// helpers
// ---------------------------------------------------------------------------
__device__ __forceinline__ uint32_t smem_u32(const void* p) {
    uint32_t a;
    asm("{ .reg .u64 t; cvta.to.shared.u64 t, %1; cvt.u32.u64 %0, t; }" : "=r"(a) : "l"(p));
    return a;
}
__device__ __forceinline__ void cp16(uint32_t dst, const void* src) {
    asm volatile("cp.async.cg.shared.global [%0], [%1], 16;" :: "r"(dst), "l"(src));
}
#define CP_COMMIT() asm volatile("cp.async.commit_group;" ::: "memory")
#define CP_WAIT1()  asm volatile("cp.async.wait_group 1;" ::: "memory")

__device__ __forceinline__ void ldsm_x4(uint32_t* r, uint32_t a) {
    asm volatile("ldmatrix.sync.aligned.m8n8.x4.shared.b16 {%0,%1,%2,%3}, [%4];"
                 : "=r"(r[0]), "=r"(r[1]), "=r"(r[2]), "=r"(r[3]) : "r"(a));
}
__device__ __forceinline__ void ldsm_x4_t(uint32_t* r, uint32_t a) {
    asm volatile("ldmatrix.sync.aligned.m8n8.x4.trans.shared.b16 {%0,%1,%2,%3}, [%4];"
                 : "=r"(r[0]), "=r"(r[1]), "=r"(r[2]), "=r"(r[3]) : "r"(a));
}
__device__ __forceinline__ void mma_f16(float* d, const uint32_t* a, const uint32_t* b) {
    asm volatile(
        "mma.sync.aligned.m16n8k16.row.col.f32.f16.f16.f32 "
        "{%0,%1,%2,%3}, {%4,%5,%6,%7}, {%8,%9}, {%0,%1,%2,%3};"
        : "+f"(d[0]), "+f"(d[1]), "+f"(d[2]), "+f"(d[3])
        : "r"(a[0]), "r"(a[1]), "r"(a[2]), "r"(a[3]), "r"(b[0]), "r"(b[1]));
}
__device__ __forceinline__ uint32_t pack_h2(float x, float y) {
    __half2 h = __floats2half2_rn(x, y);
    return *reinterpret_cast<uint32_t*>(&h);
}
// token index m, channel c -> BCHW flat index
__device__ __forceinline__ int bchw_idx(int m, int c) {
    const int wi = m / NTOK;
    const int n  = m % NTOK;
    const int b  = wi >> 4;
    const int q  = wi & 15;
    const int h  = (q >> 2) * WS + n / WS;
    const int w  = (q & 3) * WS + n % WS;
    return ((b * DIM + c) * HH + h) * WW + w;
}

// ---------------------------------------------------------------------------
// 0) all four weight conversions in ONE launch
// ---------------------------------------------------------------------------
__global__ void cvtw_all_kernel(const float* __restrict__ qkv_w,
                                const float* __restrict__ proj_w,
                                const float* __restrict__ fc1_w,
                                const float* __restrict__ fc2_w,
                                __half* __restrict__ dst)
{
    int i = blockIdx.x * blockDim.x + threadIdx.x;
    if (i >= 1769472) return;
    float v;
    if (i < WOFF_PROJ)                v = qkv_w[i];
    else if (i < WOFF_FC1)            v = proj_w[i - WOFF_PROJ];
    else if (i < WOFF_FC2)            v = fc1_w[i - WOFF_FC1];
    else                              v = fc2_w[i - WOFF_FC2];
    dst[i] = __float2half_rn(v);
}

// ---------------------------------------------------------------------------
// 1) depthwise 3x3 conv PE + residual -> windowed (wi,n,c)
//    4 output rows per CTA (6 input rows): x re-read 3x -> 1.5x
//    grid (DIM/8, HH/4, BATCH), block (8, 56)
// ---------------------------------------------------------------------------
__global__ void conv_pe_kernel(const float* __restrict__ x,
                               const float* __restrict__ cw,
                               const float* __restrict__ cb,
                               float* __restrict__ X0)
{
    const int cg = blockIdx.x * 8;
    const int h0 = blockIdx.y * 4;
    const int b  = blockIdx.z;

    __shared__ float sm[8][6][58];

    const int tid = threadIdx.y * 8 + threadIdx.x;
    const int lc  = tid / 56;
    const int lw  = tid % 56;

    const float* xp = x + ((size_t)(b * DIM + cg + lc) * HH) * WW;
#pragma unroll
    for (int r = 0; r < 6; r++) {
        int hh = h0 - 1 + r;
        float v = (hh >= 0 && hh < HH) ? xp[hh * WW + lw] : 0.0f;
        sm[lc][r][lw + 1] = v;
        if (lw == 0)  sm[lc][r][0]  = 0.0f;
        if (lw == 55) sm[lc][r][57] = 0.0f;
    }
    __syncthreads();

    const int c = threadIdx.x;
    const int w = threadIdx.y;

    float wreg[9];
    const float* cwp = cw + (size_t)(cg + c) * 9;
#pragma unroll
    for (int i = 0; i < 9; i++) wreg[i] = cwp[i];
    const float cbv = cb[cg + c];

#pragma unroll
    for (int j = 0; j < 4; j++) {
        const int h = h0 + j;
        float pe = 0.0f;
#pragma unroll
        for (int kh = 0; kh < 3; kh++)
#pragma unroll
            for (int kw = 0; kw < 3; kw++)
                pe += wreg[kh * 3 + kw] * sm[c][j + kh][w + kw];

        const float val = sm[c][j + 1][w + 1] + pe + cbv;

        const int wi = (b * 4 + h / WS) * 4 + (w / WS);
        const int n  = (h % WS) * WS + (w % WS);
        X0[((size_t)wi * NTOK + n) * DIM + cg + c] = val;
    }
}

// ---------------------------------------------------------------------------
// 2) LayerNorm; fp16 output (GEMM A operand)
// ---------------------------------------------------------------------------
__global__ void ln_kernel(const float* __restrict__ X,
                          const float* __restrict__ gamma,
                          const float* __restrict__ beta,
                          __half* __restrict__ Y)
{
    const int warp = (blockIdx.x * blockDim.x + threadIdx.x) >> 5;
    const int lane = threadIdx.x & 31;
    if (warp >= TOK) return;

    const float* xp = X + (size_t)warp * DIM;
    float v[12];
    float s = 0.0f;
#pragma unroll
    for (int k = 0; k < 12; k++) { v[k] = xp[lane + 32 * k]; s += v[k]; }
#pragma unroll
    for (int o = 16; o; o >>= 1) s += __shfl_xor_sync(0xffffffffu, s, o);
    const float mean = s * (1.0f / DIM);

    float q = 0.0f;
#pragma unroll
    for (int k = 0; k < 12; k++) { float d = v[k] - mean; q += d * d; }
#pragma unroll
    for (int o = 16; o; o >>= 1) q += __shfl_xor_sync(0xffffffffu, q, o);
    const float inv = rsqrtf(q * (1.0f / DIM) + 1e-5f);

    __half* yp = Y + (size_t)warp * DIM;
#pragma unroll
    for (int k = 0; k < 12; k++) {
        int c = lane + 32 * k;
        yp[c] = __float2half_rn((v[k] - mean) * inv * gamma[c] + beta[c]);
    }
}

// ---------------------------------------------------------------------------
// 3) FP16 mma.sync GEMM: C[M,N] = act(A[M,K] @ W[N,K]^T + bias) (+ R)
//    CTA 128x128, BK=64, 8 warps (2m x 4n), warp 64x32.  [R7/R10 config]
//    3-stage cp.async (110.6KB) -> 2 CTAs/SM (16 warps/SM). 144B odd rows.
//    Output modes: Ch fp16 | Cf fp32 (+R) | bchw!=0: scatter to BCHW out (+R)
// ---------------------------------------------------------------------------
#define BM 128
#define BN 128
#define BK 64
#define ROW_B 144                            // 9 granules, odd -> conflict-free
#define A_BYTES (128 * ROW_B)                // 18432
#define STAGE_B (2 * A_BYTES)                // 36864
#define NSTAGE  3
#define GEMM_SMEM (NSTAGE * STAGE_B)         // 110592

__global__ __launch_bounds__(256, 2)
void hgemm_kernel(const __half* __restrict__ A,
                  const __half* __restrict__ W,
                  const float* __restrict__ bias,
                  const float* __restrict__ R,
                  float* __restrict__ Cf,
                  __half* __restrict__ Ch,
                  int M, int N, int K, int act, int bchw)
{
    extern __shared__ char smc[];
    const uint32_t smem_base = smem_u32(smc);
    const int tid  = threadIdx.x;
    const int lane = tid & 31;
    const int wid  = tid >> 5;
    const int bm = blockIdx.y * BM;
    const int bn = blockIdx.x * BN;

    const int warp_m = (wid & 1) * 64;
    const int warp_n = (wid >> 1) * 32;

    float acc[4][4][4];
#pragma unroll
    for (int im = 0; im < 4; im++)
#pragma unroll
        for (int in = 0; in < 4; in++)
#pragma unroll
            for (int j = 0; j < 4; j++) acc[im][in][j] = 0.0f;

    // ldmatrix lane geometry
    const int g  = lane >> 3;
    const int r8 = lane & 7;
    const int a_row = warp_m + (g & 1) * 8 + r8;     // + im*16
    const int a_cg  = g >> 1;                        // 16B chunk within k16
    const int b_row = warp_n + (g >> 1) * 8 + r8;    // + inp*16
    const int b_cg  = g & 1;

    const int NC = K >> 6;

    // fill: thread t -> row t>>1 (A and B), chunk quad (t&1)*4
    const int fr  = tid >> 1;
    const int fc0 = (tid & 1) * 4;
    auto fill = [&](int kc, int st) {
        const int k0 = kc << 6;
        const uint32_t sb = smem_base + (uint32_t)st * STAGE_B;
        const __half* Ag = A + (size_t)(bm + fr) * K + k0;
        const __half* Wg = W + (size_t)(bn + fr) * K + k0;
#pragma unroll
        for (int c = 0; c < 4; c++) {
            const int cc = fc0 + c;
            const uint32_t so = (uint32_t)(fr * ROW_B + cc * 16);
            cp16(sb + so, Ag + cc * 8);
            cp16(sb + A_BYTES + so, Wg + cc * 8);
        }
    };

    fill(0, 0); CP_COMMIT();
    fill(1, 1); CP_COMMIT();

    for (int kc = 0; kc < NC; kc++) {
        CP_WAIT1();
        __syncthreads();

        if (kc + 2 < NC) fill(kc + 2, (kc + 2) % NSTAGE);
        CP_COMMIT();                      // unconditional: constant depth

        const uint32_t ab = smem_base + (uint32_t)(kc % NSTAGE) * STAGE_B;
        const uint32_t bb = ab + A_BYTES;

#pragma unroll
        for (int s = 0; s < 4; s++) {
            uint32_t af[4][4], bf[2][4];
#pragma unroll
            for (int im = 0; im < 4; im++)
                ldsm_x4(af[im], ab + (uint32_t)((a_row + im * 16) * ROW_B +
                                                (s * 2 + a_cg) * 16));
#pragma unroll
            for (int inp = 0; inp < 2; inp++)
                ldsm_x4(bf[inp], bb + (uint32_t)((b_row + inp * 16) * ROW_B +
                                                 (s * 2 + b_cg) * 16));
#pragma unroll
            for (int im = 0; im < 4; im++)
#pragma unroll
                for (int in = 0; in < 4; in++)
                    mma_f16(acc[im][in], af[im], &bf[in >> 1][(in & 1) * 2]);
        }
    }

    // epilogue
    const int rq = lane >> 2;
    const int cq = (lane & 3) * 2;
#pragma unroll
    for (int im = 0; im < 4; im++) {
        const int row0 = bm + warp_m + im * 16 + rq;
#pragma unroll
        for (int in = 0; in < 4; in++) {
            const int col = bn + warp_n + in * 8 + cq;
            const float2 bv = *(const float2*)(bias + col);
            float v0 = acc[im][in][0] + bv.x;
            float v1 = acc[im][in][1] + bv.y;
            float v2 = acc[im][in][2] + bv.x;
            float v3 = acc[im][in][3] + bv.y;
            if (act == 1) {
                v0 = 0.5f * v0 * (1.0f + erff(v0 * 0.70710678118654752f));
                v1 = 0.5f * v1 * (1.0f + erff(v1 * 0.70710678118654752f));
                v2 = 0.5f * v2 * (1.0f + erff(v2 * 0.70710678118654752f));
                v3 = 0.5f * v3 * (1.0f + erff(v3 * 0.70710678118654752f));
            }
            if (Ch) {
                *(__half2*)(Ch + (size_t)row0 * N + col) =
                    __halves2half2(__float2half_rn(v0), __float2half_rn(v1));
                *(__half2*)(Ch + (size_t)(row0 + 8) * N + col) =
                    __halves2half2(__float2half_rn(v2), __float2half_rn(v3));
            } else {
                if (R) {
                    const float2 r0 = *(const float2*)(R + (size_t)row0 * N + col);
                    const float2 r1 = *(const float2*)(R + (size_t)(row0 + 8) * N + col);
                    v0 += r0.x; v1 += r0.y; v2 += r1.x; v3 += r1.y;
                }
                if (bchw) {
                    // scatter to BCHW: lanes rq=0..7 -> 8 consecutive w (32B sectors)
                    Cf[bchw_idx(row0,     col)]     = v0;
                    Cf[bchw_idx(row0,     col + 1)] = v1;
                    Cf[bchw_idx(row0 + 8, col)]     = v2;
                    Cf[bchw_idx(row0 + 8, col + 1)] = v3;
                } else {
                    *(float2*)(Cf + (size_t)row0 * N + col)       = make_float2(v0, v1);
                    *(float2*)(Cf + (size_t)(row0 + 8) * N + col) = make_float2(v2, v3);
                }
            }
        }
    }
}

// ---------------------------------------------------------------------------
// 4) Window attention, full fp16 mma. 128 threads (4 warps), occupancy 2.
//    S accumulators repack DIRECTLY into PV A-fragments (no P smem).
// ---------------------------------------------------------------------------
#define AQ_STR 40
#define AROWS  208
#define ATTN_SMEM (3 * AROWS * AQ_STR * 2)      // 49920 B

__global__ __launch_bounds__(128, 2)
void attn_h_kernel(const __half* __restrict__ QKV, __half* __restrict__ ATT)
{
    const int wi  = blockIdx.x / NH;
    const int hdi = blockIdx.x % NH;

    extern __shared__ __half shh[];
    __half* qs = shh;
    __half* ks = qs + AROWS * AQ_STR;
    __half* vs = ks + AROWS * AQ_STR;

    const int tid  = threadIdx.x;
    const int warp = tid >> 5;
    const int lane = tid & 31;
    const float scale = 0.1767766952966369f;   // 1/sqrt(32)

    const __half* base = QKV + (size_t)wi * NTOK * (3 * DIM) + hdi * HD;
    for (int idx = tid; idx < AROWS * 4; idx += 128) {
        const int row = idx >> 2, c = idx & 3;
        uint4 q = make_uint4(0, 0, 0, 0), k = q, v = q;
        if (row < NTOK) {
            const __half* src = base + (size_t)row * (3 * DIM) + c * 8;
            q = *(const uint4*)(src);
            k = *(const uint4*)(src + DIM);
            v = *(const uint4*)(src + 2 * DIM);
        }
        *(uint4*)(qs + row * AQ_STR + c * 8) = q;
        *(uint4*)(ks + row * AQ_STR + c * 8) = k;
        *(uint4*)(vs + row * AQ_STR + c * 8) = v;
    }
    __syncthreads();

    const uint32_t qb = smem_u32(qs);
    const uint32_t kb = smem_u32(ks);
    const uint32_t vb = smem_u32(vs);

    const int g  = lane >> 3;
    const int r8 = lane & 7;
    const int a_row_off = (g & 1) * 8 + r8;
    const int a_cg      = (g >> 1) * 16;
    const int b_row_off = (g >> 1) * 8 + r8;
    const int b_cg      = (g & 1) * 16;

    const int rq  = lane >> 2;
    const int cq2 = (lane & 3) * 2;

    for (int t = warp; t < 13; t += 4) {
        const int m0 = t * 16;

        uint32_t af[2][4];
#pragma unroll
        for (int s = 0; s < 2; s++)
            ldsm_x4(af[s], qb + (uint32_t)((m0 + a_row_off) * 80 + a_cg + s * 32));

        float c[26][4];
#pragma unroll
        for (int nt = 0; nt < 26; nt++) { c[nt][0] = c[nt][1] = c[nt][2] = c[nt][3] = 0.f; }
#pragma unroll
        for (int np = 0; np < 13; np++) {
#pragma unroll
            for (int s = 0; s < 2; s++) {
                uint32_t bf[4];
                ldsm_x4(bf, kb + (uint32_t)((np * 16 + b_row_off) * 80 + b_cg + s * 32));
                mma_f16(c[2 * np],     af[s], &bf[0]);
                mma_f16(c[2 * np + 1], af[s], &bf[2]);
            }
        }

        float mx0 = -1e30f, mx1 = -1e30f;
#pragma unroll
        for (int nt = 0; nt < 26; nt++) {
            const int col = nt * 8 + cq2;
            if (col < NTOK)     { mx0 = fmaxf(mx0, c[nt][0]); mx1 = fmaxf(mx1, c[nt][2]); }
            if (col + 1 < NTOK) { mx0 = fmaxf(mx0, c[nt][1]); mx1 = fmaxf(mx1, c[nt][3]); }
        }
        mx0 = fmaxf(mx0, __shfl_xor_sync(0xffffffffu, mx0, 1));
        mx0 = fmaxf(mx0, __shfl_xor_sync(0xffffffffu, mx0, 2));
        mx1 = fmaxf(mx1, __shfl_xor_sync(0xffffffffu, mx1, 1));
        mx1 = fmaxf(mx1, __shfl_xor_sync(0xffffffffu, mx1, 2));

        uint32_t ph[26][2];
        float sum0 = 0.f, sum1 = 0.f;
#pragma unroll
        for (int nt = 0; nt < 26; nt++) {
            const int col = nt * 8 + cq2;
            float p0 = (col < NTOK)     ? __expf((c[nt][0] - mx0) * scale) : 0.f;
            float p1 = (col + 1 < NTOK) ? __expf((c[nt][1] - mx0) * scale) : 0.f;
            float p2 = (col < NTOK)     ? __expf((c[nt][2] - mx1) * scale) : 0.f;
            float p3 = (col + 1 < NTOK) ? __expf((c[nt][3] - mx1) * scale) : 0.f;
            sum0 += p0 + p1;
            sum1 += p2 + p3;
            ph[nt][0] = pack_h2(p0, p1);
            ph[nt][1] = pack_h2(p2, p3);
        }
        sum0 += __shfl_xor_sync(0xffffffffu, sum0, 1);
        sum0 += __shfl_xor_sync(0xffffffffu, sum0, 2);
        sum1 += __shfl_xor_sync(0xffffffffu, sum1, 1);
        sum1 += __shfl_xor_sync(0xffffffffu, sum1, 2);

        float o[4][4];
#pragma unroll
        for (int n = 0; n < 4; n++) { o[n][0] = o[n][1] = o[n][2] = o[n][3] = 0.f; }
#pragma unroll
        for (int kt = 0; kt < 13; kt++) {
            uint32_t a[4] = { ph[2 * kt][0], ph[2 * kt][1],
                              ph[2 * kt + 1][0], ph[2 * kt + 1][1] };
            uint32_t v0f[4], v1f[4];
            ldsm_x4_t(v0f, vb + (uint32_t)((kt * 16 + a_row_off) * 80 + a_cg));
            ldsm_x4_t(v1f, vb + (uint32_t)((kt * 16 + a_row_off) * 80 + a_cg + 32));
            mma_f16(o[0], a, &v0f[0]);
            mma_f16(o[1], a, &v0f[2]);
            mma_f16(o[2], a, &v1f[0]);
            mma_f16(o[3], a, &v1f[2]);
        }

        const float inv0 = 1.0f / sum0;
        const float inv1 = 1.0f / sum1;
        const int r0 = m0 + rq, r1 = m0 + rq + 8;
#pragma unroll
        for (int n = 0; n < 4; n++) {
            const int col = hdi * HD + n * 8 + cq2;
            if (r0 < NTOK)
                *(__half2*)(ATT + ((size_t)wi * NTOK + r0) * DIM + col) =
                    __halves2half2(__float2half_rn(o[n][0] * inv0), __float2half_rn(o[n][1] * inv0));
            if (r1 < NTOK)
                *(__half2*)(ATT + ((size_t)wi * NTOK + r1) * DIM + col) =
                    __halves2half2(__float2half_rn(o[n][2] * inv1), __float2half_rn(o[n][3] * inv1));
        }
    }
}

// ---------------------------------------------------------------------------
// Launch
// ---------------------------------------------------------------------------
extern "C" void kernel_launch(void* const* d_in, const int* in_sizes, int n_in,
                              void* d_out, int out_size)
{
    const float* x      = (const float*)d_in[0];
    const float* conv_w = (const float*)d_in[1];
    const float* conv_b = (const float*)d_in[2];
    const float* ln1_g  = (const float*)d_in[3];
    const float* ln1_b  = (const float*)d_in[4];
    const float* qkv_w  = (const float*)d_in[5];
    const float* qkv_b  = (const float*)d_in[6];
    const float* proj_w = (const float*)d_in[7];
    const float* proj_b = (const float*)d_in[8];
    const float* ln2_g  = (const float*)d_in[9];
    const float* ln2_b  = (const float*)d_in[10];
    const float* fc1_w  = (const float*)d_in[11];
    const float* fc1_b  = (const float*)d_in[12];
    const float* fc2_w  = (const float*)d_in[13];
    const float* fc2_b  = (const float*)d_in[14];
    float* out = (float*)d_out;

    float *X0, *X1;
    __half *Y, *QKV, *ATT, *F, *Wh;
    cudaGetSymbolAddress((void**)&X0,  g_X0);
    cudaGetSymbolAddress((void**)&Y,   g_Y);
    cudaGetSymbolAddress((void**)&QKV, g_QKV);
    cudaGetSymbolAddress((void**)&ATT, g_ATT);
    cudaGetSymbolAddress((void**)&X1,  g_X1);
    cudaGetSymbolAddress((void**)&F,   g_F);
    cudaGetSymbolAddress((void**)&Wh,  g_Wh);

    cudaFuncSetAttribute(attn_h_kernel, cudaFuncAttributeMaxDynamicSharedMemorySize, ATTN_SMEM);
    cudaFuncSetAttribute(hgemm_kernel, cudaFuncAttributeMaxDynamicSharedMemorySize, GEMM_SMEM);

    // 0) fp16 weights (single launch)
    cvtw_all_kernel<<<(1769472 + 255) / 256, 256>>>(qkv_w, proj_w, fc1_w, fc2_w, Wh);

    // 1) conv PE + residual -> X0 (4 rows per CTA)
    conv_pe_kernel<<<dim3(DIM / 8, HH / 4, BATCH), dim3(8, 56)>>>(x, conv_w, conv_b, X0);

    // 2) LN1 -> Y (fp16)
    ln_kernel<<<TOK / 8, 256>>>(X0, ln1_g, ln1_b, Y);

    // 3) QKV GEMM (fp16 in, fp16 out)
    hgemm_kernel<<<dim3(3 * DIM / BN, TOK / BM), 256, GEMM_SMEM>>>(
        Y, Wh + WOFF_QKV, qkv_b, nullptr, nullptr, QKV, TOK, 3 * DIM, DIM, 0, 0);

    // 4) window attention -> ATT (fp16)
    attn_h_kernel<<<NWIN * NH, 128, ATTN_SMEM>>>(QKV, ATT);

    // 5) proj GEMM + residual(X0) -> X1 (fp32)
    hgemm_kernel<<<dim3(DIM / BN, TOK / BM), 256, GEMM_SMEM>>>(
        ATT, Wh + WOFF_PROJ, proj_b, X0, X1, nullptr, TOK, DIM, DIM, 0, 0);

    // 6) LN2 -> Y (fp16)
    ln_kernel<<<TOK / 8, 256>>>(X1, ln2_g, ln2_b, Y);

    // 7) FC1 GEMM + GELU -> F (fp16)
    hgemm_kernel<<<dim3(4 * DIM / BN, TOK / BM), 256, GEMM_SMEM>>>(
        Y, Wh + WOFF_FC1, fc1_b, nullptr, nullptr, F, TOK, 4 * DIM, DIM, 1, 0);

    // 8) FC2 GEMM + residual(X1) -> out, scattered directly to BCHW
    hgemm_kernel<<<dim3(DIM / BN, TOK / BM), 256, GEMM_SMEM>>>(
        F, Wh + WOFF_FC2, fc2_b, X1, out, nullptr, TOK, DIM, 4 * DIM, 0, 1);
}

// round 12
// speedup vs baseline: 1.2853x; 1.0002x over previous
#include <cuda_runtime.h>
#include <cuda_bf16.h>
#include <cuda_fp16.h>
#include <math.h>
#include <cstdint>

// ---------------------------------------------------------------------------
// Problem constants
// ---------------------------------------------------------------------------
#define DIM   384
#define NH    12
#define HD    32
#define WS    14
#define BATCH 16
#define HH    56
#define WW    56
#define NWIN  256
#define NTOK  196
#define TOK   50176          // NWIN*NTOK

// ---------------------------------------------------------------------------
// Scratch
// ---------------------------------------------------------------------------
__device__ __align__(16) float  g_X0 [(size_t)TOK * DIM];
__device__ __align__(16) __half g_Y  [(size_t)TOK * DIM];
__device__ __align__(16) __half g_QKV[(size_t)TOK * 3 * DIM];
__device__ __align__(16) __half g_ATT[(size_t)TOK * DIM];
__device__ __align__(16) float  g_X1 [(size_t)TOK * DIM];
__device__ __align__(16) __half g_F  [(size_t)TOK * 4 * DIM];
__device__ __align__(16) __half g_Wh [1769472];          // fp16 weights

#define N_QKV  (3 * DIM * DIM)
#define N_PROJ (DIM * DIM)
#define N_FC   (4 * DIM * DIM)
#define WOFF_QKV  0
#define WOFF_PROJ N_QKV
#define WOFF_FC1  (WOFF_PROJ + N_PROJ)
#define WOFF_FC2  (WOFF_FC1 + N_FC)

// ---------------------------------------------------------------------------
// helpers
// ---------------------------------------------------------------------------
__device__ __forceinline__ uint32_t smem_u32(const void* p) {
    uint32_t a;
    asm("{ .reg .u64 t; cvta.to.shared.u64 t, %1; cvt.u32.u64 %0, t; }" : "=r"(a) : "l"(p));
    return a;
}
__device__ __forceinline__ void cp16(uint32_t dst, const void* src) {
    asm volatile("cp.async.cg.shared.global [%0], [%1], 16;" :: "r"(dst), "l"(src));
}
#define CP_COMMIT() asm volatile("cp.async.commit_group;" ::: "memory")
#define CP_WAIT1()  asm volatile("cp.async.wait_group 1;" ::: "memory")

__device__ __forceinline__ void ldsm_x4(uint32_t* r, uint32_t a) {
    asm volatile("ldmatrix.sync.aligned.m8n8.x4.shared.b16 {%0,%1,%2,%3}, [%4];"
                 : "=r"(r[0]), "=r"(r[1]), "=r"(r[2]), "=r"(r[3]) : "r"(a));
}
__device__ __forceinline__ void ldsm_x4_t(uint32_t* r, uint32_t a) {
    asm volatile("ldmatrix.sync.aligned.m8n8.x4.trans.shared.b16 {%0,%1,%2,%3}, [%4];"
                 : "=r"(r[0]), "=r"(r[1]), "=r"(r[2]), "=r"(r[3]) : "r"(a));
}
__device__ __forceinline__ void mma_f16(float* d, const uint32_t* a, const uint32_t* b) {
    asm volatile(
        "mma.sync.aligned.m16n8k16.row.col.f32.f16.f16.f32 "
        "{%0,%1,%2,%3}, {%4,%5,%6,%7}, {%8,%9}, {%0,%1,%2,%3};"
        : "+f"(d[0]), "+f"(d[1]), "+f"(d[2]), "+f"(d[3])
        : "r"(a[0]), "r"(a[1]), "r"(a[2]), "r"(a[3]), "r"(b[0]), "r"(b[1]));
}
__device__ __forceinline__ uint32_t pack_h2(float x, float y) {
    __half2 h = __floats2half2_rn(x, y);
    return *reinterpret_cast<uint32_t*>(&h);
}
// token index m, channel c -> BCHW flat index
__device__ __forceinline__ int bchw_idx(int m, int c) {
    const int wi = m / NTOK;
    const int n  = m % NTOK;
    const int b  = wi >> 4;
    const int q  = wi & 15;
    const int h  = (q >> 2) * WS + n / WS;
    const int w  = (q & 3) * WS + n % WS;
    return ((b * DIM + c) * HH + h) * WW + w;
}

// ---------------------------------------------------------------------------
// 0) all four weight conversions in ONE launch
// ---------------------------------------------------------------------------
__global__ void cvtw_all_kernel(const float* __restrict__ qkv_w,
                                const float* __restrict__ proj_w,
                                const float* __restrict__ fc1_w,
                                const float* __restrict__ fc2_w,
                                __half* __restrict__ dst)
{
    int i = blockIdx.x * blockDim.x + threadIdx.x;
    if (i >= 1769472) return;
    float v;
    if (i < WOFF_PROJ)                v = qkv_w[i];
    else if (i < WOFF_FC1)            v = proj_w[i - WOFF_PROJ];
    else if (i < WOFF_FC2)            v = fc1_w[i - WOFF_FC1];
    else                              v = fc2_w[i - WOFF_FC2];
    dst[i] = __float2half_rn(v);
}

// ---------------------------------------------------------------------------
// 1) depthwise 3x3 conv PE + residual -> windowed (wi,n,c)
//    4 output rows per CTA (6 input rows)
// ---------------------------------------------------------------------------
__global__ void conv_pe_kernel(const float* __restrict__ x,
                               const float* __restrict__ cw,
                               const float* __restrict__ cb,
                               float* __restrict__ X0)
{
    const int cg = blockIdx.x * 8;
    const int h0 = blockIdx.y * 4;
    const int b  = blockIdx.z;

    __shared__ float sm[8][6][58];

    const int tid = threadIdx.y * 8 + threadIdx.x;
    const int lc  = tid / 56;
    const int lw  = tid % 56;

    const float* xp = x + ((size_t)(b * DIM + cg + lc) * HH) * WW;
#pragma unroll
    for (int r = 0; r < 6; r++) {
        int hh = h0 - 1 + r;
        float v = (hh >= 0 && hh < HH) ? xp[hh * WW + lw] : 0.0f;
        sm[lc][r][lw + 1] = v;
        if (lw == 0)  sm[lc][r][0]  = 0.0f;
        if (lw == 55) sm[lc][r][57] = 0.0f;
    }
    __syncthreads();

    const int c = threadIdx.x;
    const int w = threadIdx.y;

    float wreg[9];
    const float* cwp = cw + (size_t)(cg + c) * 9;
#pragma unroll
    for (int i = 0; i < 9; i++) wreg[i] = cwp[i];
    const float cbv = cb[cg + c];

#pragma unroll
    for (int j = 0; j < 4; j++) {
        const int h = h0 + j;
        float pe = 0.0f;
#pragma unroll
        for (int kh = 0; kh < 3; kh++)
#pragma unroll
            for (int kw = 0; kw < 3; kw++)
                pe += wreg[kh * 3 + kw] * sm[c][j + kh][w + kw];

        const float val = sm[c][j + 1][w + 1] + pe + cbv;

        const int wi = (b * 4 + h / WS) * 4 + (w / WS);
        const int n  = (h % WS) * WS + (w % WS);
        X0[((size_t)wi * NTOK + n) * DIM + cg + c] = val;
    }
}

// ---------------------------------------------------------------------------
// 2) LayerNorm; fp16 output (GEMM A operand)
// ---------------------------------------------------------------------------
__global__ void ln_kernel(const float* __restrict__ X,
                          const float* __restrict__ gamma,
                          const float* __restrict__ beta,
                          __half* __restrict__ Y)
{
    const int warp = (blockIdx.x * blockDim.x + threadIdx.x) >> 5;
    const int lane = threadIdx.x & 31;
    if (warp >= TOK) return;

    const float* xp = X + (size_t)warp * DIM;
    float v[12];
    float s = 0.0f;
#pragma unroll
    for (int k = 0; k < 12; k++) { v[k] = xp[lane + 32 * k]; s += v[k]; }
#pragma unroll
    for (int o = 16; o; o >>= 1) s += __shfl_xor_sync(0xffffffffu, s, o);
    const float mean = s * (1.0f / DIM);

    float q = 0.0f;
#pragma unroll
    for (int k = 0; k < 12; k++) { float d = v[k] - mean; q += d * d; }
#pragma unroll
    for (int o = 16; o; o >>= 1) q += __shfl_xor_sync(0xffffffffu, q, o);
    const float inv = rsqrtf(q * (1.0f / DIM) + 1e-5f);

    __half* yp = Y + (size_t)warp * DIM;
#pragma unroll
    for (int k = 0; k < 12; k++) {
        int c = lane + 32 * k;
        yp[c] = __float2half_rn((v[k] - mean) * inv * gamma[c] + beta[c]);
    }
}

// ---------------------------------------------------------------------------
// 3) FP16 mma.sync GEMM (R7/R10 config, frozen)
// ---------------------------------------------------------------------------
#define BM 128
#define BN 128
#define BK 64
#define ROW_B 144
#define A_BYTES (128 * ROW_B)
#define STAGE_B (2 * A_BYTES)
#define NSTAGE  3
#define GEMM_SMEM (NSTAGE * STAGE_B)

__global__ __launch_bounds__(256, 2)
void hgemm_kernel(const __half* __restrict__ A,
                  const __half* __restrict__ W,
                  const float* __restrict__ bias,
                  const float* __restrict__ R,
                  float* __restrict__ Cf,
                  __half* __restrict__ Ch,
                  int M, int N, int K, int act, int bchw)
{
    extern __shared__ char smc[];
    const uint32_t smem_base = smem_u32(smc);
    const int tid  = threadIdx.x;
    const int lane = tid & 31;
    const int wid  = tid >> 5;
    const int bm = blockIdx.y * BM;
    const int bn = blockIdx.x * BN;

    const int warp_m = (wid & 1) * 64;
    const int warp_n = (wid >> 1) * 32;

    float acc[4][4][4];
#pragma unroll
    for (int im = 0; im < 4; im++)
#pragma unroll
        for (int in = 0; in < 4; in++)
#pragma unroll
            for (int j = 0; j < 4; j++) acc[im][in][j] = 0.0f;

    const int g  = lane >> 3;
    const int r8 = lane & 7;
    const int a_row = warp_m + (g & 1) * 8 + r8;
    const int a_cg  = g >> 1;
    const int b_row = warp_n + (g >> 1) * 8 + r8;
    const int b_cg  = g & 1;

    const int NC = K >> 6;

    const int fr  = tid >> 1;
    const int fc0 = (tid & 1) * 4;
    auto fill = [&](int kc, int st) {
        const int k0 = kc << 6;
        const uint32_t sb = smem_base + (uint32_t)st * STAGE_B;
        const __half* Ag = A + (size_t)(bm + fr) * K + k0;
        const __half* Wg = W + (size_t)(bn + fr) * K + k0;
#pragma unroll
        for (int c = 0; c < 4; c++) {
            const int cc = fc0 + c;
            const uint32_t so = (uint32_t)(fr * ROW_B + cc * 16);
            cp16(sb + so, Ag + cc * 8);
            cp16(sb + A_BYTES + so, Wg + cc * 8);
        }
    };

    fill(0, 0); CP_COMMIT();
    fill(1, 1); CP_COMMIT();

    for (int kc = 0; kc < NC; kc++) {
        CP_WAIT1();
        __syncthreads();

        if (kc + 2 < NC) fill(kc + 2, (kc + 2) % NSTAGE);
        CP_COMMIT();

        const uint32_t ab = smem_base + (uint32_t)(kc % NSTAGE) * STAGE_B;
        const uint32_t bb = ab + A_BYTES;

#pragma unroll
        for (int s = 0; s < 4; s++) {
            uint32_t af[4][4], bf[2][4];
#pragma unroll
            for (int im = 0; im < 4; im++)
                ldsm_x4(af[im], ab + (uint32_t)((a_row + im * 16) * ROW_B +
                                                (s * 2 + a_cg) * 16));
#pragma unroll
            for (int inp = 0; inp < 2; inp++)
                ldsm_x4(bf[inp], bb + (uint32_t)((b_row + inp * 16) * ROW_B +
                                                 (s * 2 + b_cg) * 16));
#pragma unroll
            for (int im = 0; im < 4; im++)
#pragma unroll
                for (int in = 0; in < 4; in++)
                    mma_f16(acc[im][in], af[im], &bf[in >> 1][(in & 1) * 2]);
        }
    }

    const int rq = lane >> 2;
    const int cq = (lane & 3) * 2;
#pragma unroll
    for (int im = 0; im < 4; im++) {
        const int row0 = bm + warp_m + im * 16 + rq;
#pragma unroll
        for (int in = 0; in < 4; in++) {
            const int col = bn + warp_n + in * 8 + cq;
            const float2 bv = *(const float2*)(bias + col);
            float v0 = acc[im][in][0] + bv.x;
            float v1 = acc[im][in][1] + bv.y;
            float v2 = acc[im][in][2] + bv.x;
            float v3 = acc[im][in][3] + bv.y;
            if (act == 1) {
                v0 = 0.5f * v0 * (1.0f + erff(v0 * 0.70710678118654752f));
                v1 = 0.5f * v1 * (1.0f + erff(v1 * 0.70710678118654752f));
                v2 = 0.5f * v2 * (1.0f + erff(v2 * 0.70710678118654752f));
                v3 = 0.5f * v3 * (1.0f + erff(v3 * 0.70710678118654752f));
            }
            if (Ch) {
                *(__half2*)(Ch + (size_t)row0 * N + col) =
                    __halves2half2(__float2half_rn(v0), __float2half_rn(v1));
                *(__half2*)(Ch + (size_t)(row0 + 8) * N + col) =
                    __halves2half2(__float2half_rn(v2), __float2half_rn(v3));
            } else {
                if (R) {
                    const float2 r0 = *(const float2*)(R + (size_t)row0 * N + col);
                    const float2 r1 = *(const float2*)(R + (size_t)(row0 + 8) * N + col);
                    v0 += r0.x; v1 += r0.y; v2 += r1.x; v3 += r1.y;
                }
                if (bchw) {
                    Cf[bchw_idx(row0,     col)]     = v0;
                    Cf[bchw_idx(row0,     col + 1)] = v1;
                    Cf[bchw_idx(row0 + 8, col)]     = v2;
                    Cf[bchw_idx(row0 + 8, col + 1)] = v3;
                } else {
                    *(float2*)(Cf + (size_t)row0 * N + col)       = make_float2(v0, v1);
                    *(float2*)(Cf + (size_t)(row0 + 8) * N + col) = make_float2(v2, v3);
                }
            }
        }
    }
}

// ---------------------------------------------------------------------------
// 4) Window attention, fp16 mma, ONLINE SOFTMAX in 2 chunks (14+12 n-tiles).
//    Register diet -> 3 CTAs/SM (12 warps). 128 threads (4 warps).
// ---------------------------------------------------------------------------
#define AQ_STR 40
#define AROWS  208
#define ATTN_SMEM (3 * AROWS * AQ_STR * 2)      // 49920 B

__global__ __launch_bounds__(128, 3)
void attn_h_kernel(const __half* __restrict__ QKV, __half* __restrict__ ATT)
{
    const int wi  = blockIdx.x / NH;
    const int hdi = blockIdx.x % NH;

    extern __shared__ __half shh[];
    __half* qs = shh;
    __half* ks = qs + AROWS * AQ_STR;
    __half* vs = ks + AROWS * AQ_STR;

    const int tid  = threadIdx.x;
    const int warp = tid >> 5;
    const int lane = tid & 31;
    const float scale = 0.1767766952966369f;   // 1/sqrt(32)

    const __half* base = QKV + (size_t)wi * NTOK * (3 * DIM) + hdi * HD;
    for (int idx = tid; idx < AROWS * 4; idx += 128) {
        const int row = idx >> 2, c = idx & 3;
        uint4 q = make_uint4(0, 0, 0, 0), k = q, v = q;
        if (row < NTOK) {
            const __half* src = base + (size_t)row * (3 * DIM) + c * 8;
            q = *(const uint4*)(src);
            k = *(const uint4*)(src + DIM);
            v = *(const uint4*)(src + 2 * DIM);
        }
        *(uint4*)(qs + row * AQ_STR + c * 8) = q;
        *(uint4*)(ks + row * AQ_STR + c * 8) = k;
        *(uint4*)(vs + row * AQ_STR + c * 8) = v;
    }
    __syncthreads();

    const uint32_t qb = smem_u32(qs);
    const uint32_t kb = smem_u32(ks);
    const uint32_t vb = smem_u32(vs);

    const int g  = lane >> 3;
    const int r8 = lane & 7;
    const int a_row_off = (g & 1) * 8 + r8;
    const int a_cg      = (g >> 1) * 16;
    const int b_row_off = (g >> 1) * 8 + r8;
    const int b_cg      = (g & 1) * 16;

    const int rq  = lane >> 2;
    const int cq2 = (lane & 3) * 2;

    for (int t = warp; t < 13; t += 4) {
        const int m0 = t * 16;

        uint32_t af[2][4];
#pragma unroll
        for (int s = 0; s < 2; s++)
            ldsm_x4(af[s], qb + (uint32_t)((m0 + a_row_off) * 80 + a_cg + s * 32));

        float m0r = -1e30f, m1r = -1e30f;   // running max (raw S units)
        float s0 = 0.f, s1 = 0.f;           // running sums
        float o[4][4];
#pragma unroll
        for (int n = 0; n < 4; n++) { o[n][0] = o[n][1] = o[n][2] = o[n][3] = 0.f; }

#pragma unroll
        for (int ch = 0; ch < 2; ch++) {
            const int NT    = ch ? 12 : 14;       // n-tiles in this chunk
            const int base8 = ch ? 112 : 0;       // row/col base

            // ---- S chunk ----
            float c[14][4];
#pragma unroll
            for (int nt = 0; nt < 14; nt++) { c[nt][0] = c[nt][1] = c[nt][2] = c[nt][3] = 0.f; }
#pragma unroll
            for (int np = 0; np < 7; np++) {
                if (np >= NT / 2) break;
#pragma unroll
                for (int s = 0; s < 2; s++) {
                    uint32_t bf[4];
                    ldsm_x4(bf, kb + (uint32_t)((base8 + np * 16 + b_row_off) * 80 + b_cg + s * 32));
                    mma_f16(c[2 * np],     af[s], &bf[0]);
                    mma_f16(c[2 * np + 1], af[s], &bf[2]);
                }
            }

            // ---- chunk max (chunk 0 needs no mask: cols < 112 < 196) ----
            float mx0 = -1e30f, mx1 = -1e30f;
#pragma unroll
            for (int nt = 0; nt < 14; nt++) {
                if (nt >= NT) break;
                const int col = base8 + nt * 8 + cq2;
                const bool ok0 = (ch == 0) || (col < NTOK);
                const bool ok1 = (ch == 0) || (col + 1 < NTOK);
                if (ok0) { mx0 = fmaxf(mx0, c[nt][0]); mx1 = fmaxf(mx1, c[nt][2]); }
                if (ok1) { mx0 = fmaxf(mx0, c[nt][1]); mx1 = fmaxf(mx1, c[nt][3]); }
            }
            mx0 = fmaxf(mx0, __shfl_xor_sync(0xffffffffu, mx0, 1));
            mx0 = fmaxf(mx0, __shfl_xor_sync(0xffffffffu, mx0, 2));
            mx1 = fmaxf(mx1, __shfl_xor_sync(0xffffffffu, mx1, 1));
            mx1 = fmaxf(mx1, __shfl_xor_sync(0xffffffffu, mx1, 2));

            const float nm0 = fmaxf(m0r, mx0);
            const float nm1 = fmaxf(m1r, mx1);
            const float r0 = __expf((m0r - nm0) * scale);   // chunk 0: exp(-inf)=0
            const float r1 = __expf((m1r - nm1) * scale);
            m0r = nm0; m1r = nm1;

            // ---- exp + pack ----
            uint32_t ph[14][2];
            float cs0 = 0.f, cs1 = 0.f;
#pragma unroll
            for (int nt = 0; nt < 14; nt++) {
                if (nt >= NT) break;
                const int col = base8 + nt * 8 + cq2;
                const bool ok0 = (ch == 0) || (col < NTOK);
                const bool ok1 = (ch == 0) || (col + 1 < NTOK);
                float p0 = ok0 ? __expf((c[nt][0] - nm0) * scale) : 0.f;
                float p1 = ok1 ? __expf((c[nt][1] - nm0) * scale) : 0.f;
                float p2 = ok0 ? __expf((c[nt][2] - nm1) * scale) : 0.f;
                float p3 = ok1 ? __expf((c[nt][3] - nm1) * scale) : 0.f;
                cs0 += p0 + p1;
                cs1 += p2 + p3;
                ph[nt][0] = pack_h2(p0, p1);
                ph[nt][1] = pack_h2(p2, p3);
            }
            cs0 += __shfl_xor_sync(0xffffffffu, cs0, 1);
            cs0 += __shfl_xor_sync(0xffffffffu, cs0, 2);
            cs1 += __shfl_xor_sync(0xffffffffu, cs1, 1);
            cs1 += __shfl_xor_sync(0xffffffffu, cs1, 2);
            s0 = s0 * r0 + cs0;
            s1 = s1 * r1 + cs1;

            // ---- rescale running O ----
#pragma unroll
            for (int n = 0; n < 4; n++) {
                o[n][0] *= r0; o[n][1] *= r0;
                o[n][2] *= r1; o[n][3] *= r1;
            }

            // ---- PV chunk ----
#pragma unroll
            for (int kt = 0; kt < 7; kt++) {
                if (kt >= NT / 2) break;
                uint32_t a[4] = { ph[2 * kt][0], ph[2 * kt][1],
                                  ph[2 * kt + 1][0], ph[2 * kt + 1][1] };
                uint32_t v0f[4], v1f[4];
                ldsm_x4_t(v0f, vb + (uint32_t)((base8 + kt * 16 + a_row_off) * 80 + a_cg));
                ldsm_x4_t(v1f, vb + (uint32_t)((base8 + kt * 16 + a_row_off) * 80 + a_cg + 32));
                mma_f16(o[0], a, &v0f[0]);
                mma_f16(o[1], a, &v0f[2]);
                mma_f16(o[2], a, &v1f[0]);
                mma_f16(o[3], a, &v1f[2]);
            }
        }

        // ---- normalize + store fp16 ----
        const float inv0 = 1.0f / s0;
        const float inv1 = 1.0f / s1;
        const int rr0 = m0 + rq, rr1 = m0 + rq + 8;
#pragma unroll
        for (int n = 0; n < 4; n++) {
            const int col = hdi * HD + n * 8 + cq2;
            if (rr0 < NTOK)
                *(__half2*)(ATT + ((size_t)wi * NTOK + rr0) * DIM + col) =
                    __halves2half2(__float2half_rn(o[n][0] * inv0), __float2half_rn(o[n][1] * inv0));
            if (rr1 < NTOK)
                *(__half2*)(ATT + ((size_t)wi * NTOK + rr1) * DIM + col) =
                    __halves2half2(__float2half_rn(o[n][2] * inv1), __float2half_rn(o[n][3] * inv1));
        }
    }
}

// ---------------------------------------------------------------------------
// Launch
// ---------------------------------------------------------------------------
extern "C" void kernel_launch(void* const* d_in, const int* in_sizes, int n_in,
                              void* d_out, int out_size)
{
    const float* x      = (const float*)d_in[0];
    const float* conv_w = (const float*)d_in[1];
    const float* conv_b = (const float*)d_in[2];
    const float* ln1_g  = (const float*)d_in[3];
    const float* ln1_b  = (const float*)d_in[4];
    const float* qkv_w  = (const float*)d_in[5];
    const float* qkv_b  = (const float*)d_in[6];
    const float* proj_w = (const float*)d_in[7];
    const float* proj_b = (const float*)d_in[8];
    const float* ln2_g  = (const float*)d_in[9];
    const float* ln2_b  = (const float*)d_in[10];
    const float* fc1_w  = (const float*)d_in[11];
    const float* fc1_b  = (const float*)d_in[12];
    const float* fc2_w  = (const float*)d_in[13];
    const float* fc2_b  = (const float*)d_in[14];
    float* out = (float*)d_out;

    float *X0, *X1;
    __half *Y, *QKV, *ATT, *F, *Wh;
    cudaGetSymbolAddress((void**)&X0,  g_X0);
    cudaGetSymbolAddress((void**)&Y,   g_Y);
    cudaGetSymbolAddress((void**)&QKV, g_QKV);
    cudaGetSymbolAddress((void**)&ATT, g_ATT);
    cudaGetSymbolAddress((void**)&X1,  g_X1);
    cudaGetSymbolAddress((void**)&F,   g_F);
    cudaGetSymbolAddress((void**)&Wh,  g_Wh);

    cudaFuncSetAttribute(attn_h_kernel, cudaFuncAttributeMaxDynamicSharedMemorySize, ATTN_SMEM);
    cudaFuncSetAttribute(hgemm_kernel, cudaFuncAttributeMaxDynamicSharedMemorySize, GEMM_SMEM);

    // 0) fp16 weights (single launch)
    cvtw_all_kernel<<<(1769472 + 255) / 256, 256>>>(qkv_w, proj_w, fc1_w, fc2_w, Wh);

    // 1) conv PE + residual -> X0 (4 rows per CTA)
    conv_pe_kernel<<<dim3(DIM / 8, HH / 4, BATCH), dim3(8, 56)>>>(x, conv_w, conv_b, X0);

    // 2) LN1 -> Y (fp16)
    ln_kernel<<<TOK / 8, 256>>>(X0, ln1_g, ln1_b, Y);

    // 3) QKV GEMM (fp16 in, fp16 out)
    hgemm_kernel<<<dim3(3 * DIM / BN, TOK / BM), 256, GEMM_SMEM>>>(
        Y, Wh + WOFF_QKV, qkv_b, nullptr, nullptr, QKV, TOK, 3 * DIM, DIM, 0, 0);

    // 4) window attention -> ATT (fp16, online softmax, occ 3)
    attn_h_kernel<<<NWIN * NH, 128, ATTN_SMEM>>>(QKV, ATT);

    // 5) proj GEMM + residual(X0) -> X1 (fp32)
    hgemm_kernel<<<dim3(DIM / BN, TOK / BM), 256, GEMM_SMEM>>>(
        ATT, Wh + WOFF_PROJ, proj_b, X0, X1, nullptr, TOK, DIM, DIM, 0, 0);

    // 6) LN2 -> Y (fp16)
    ln_kernel<<<TOK / 8, 256>>>(X1, ln2_g, ln2_b, Y);

    // 7) FC1 GEMM + GELU -> F (fp16)
    hgemm_kernel<<<dim3(4 * DIM / BN, TOK / BM), 256, GEMM_SMEM>>>(
        Y, Wh + WOFF_FC1, fc1_b, nullptr, nullptr, F, TOK, 4 * DIM, DIM, 1, 0);

    // 8) FC2 GEMM + residual(X1) -> out, scattered directly to BCHW
    hgemm_kernel<<<dim3(DIM / BN, TOK / BM), 256, GEMM_SMEM>>>(
        F, Wh + WOFF_FC2, fc2_b, X1, out, nullptr, TOK, DIM, 4 * DIM, 0, 1);
}